// round 6
// baseline (speedup 1.0000x reference)
#include <cuda_runtime.h>
#include <math.h>
#include <cstdint>

#define BB   2
#define TT   2048
#define BT   4096
#define DIMC 1024
#define NH   16
#define HD   64
#define HID  4096
#define EPSV 1e-6f

// ---------------- scratch ----------------------------------------------------
__device__ float g_xn[BT * DIMC];
__device__ float g_q [BT * DIMC];
__device__ float g_k [BT * DIMC];
__device__ float g_v [BT * DIMC];
__device__ float g_ao[BT * DIMC];
__device__ float g_x1[BT * DIMC];
__device__ float g_h [BT * HID];

// ---------------- helpers -----------------------------------------------------
__device__ __forceinline__ unsigned f2tf(float f) {
    unsigned u;
    asm("cvt.rna.tf32.f32 %0, %1;" : "=r"(u) : "f"(f));
    return u;
}
__device__ __forceinline__ uint32_t smem_u32(const void* p) {
    uint32_t a;
    asm("{ .reg .u64 t; cvta.to.shared.u64 t, %1; cvt.u32.u64 %0, t; }"
        : "=r"(a) : "l"(p));
    return a;
}
__device__ __forceinline__ void mma8(float* d, const unsigned* a, const unsigned* b) {
    asm volatile(
        "mma.sync.aligned.m16n8k8.row.col.f32.tf32.tf32.f32 "
        "{%0,%1,%2,%3}, {%4,%5,%6,%7}, {%8,%9}, {%0,%1,%2,%3};"
        : "+f"(d[0]), "+f"(d[1]), "+f"(d[2]), "+f"(d[3])
        : "r"(a[0]), "r"(a[1]), "r"(a[2]), "r"(a[3]), "r"(b[0]), "r"(b[1]));
}
__device__ __forceinline__ void ldsm4(uint32_t addr, unsigned* r) {
    asm volatile("ldmatrix.sync.aligned.m8n8.x4.shared.b16 {%0,%1,%2,%3}, [%4];"
        : "=r"(r[0]), "=r"(r[1]), "=r"(r[2]), "=r"(r[3]) : "r"(addr));
}

// ---------------- RMSNorm ----------------------------------------------------
__global__ void rmsnorm_kernel(const float* __restrict__ x,
                               const float* __restrict__ g,
                               float* __restrict__ y) {
    int row = blockIdx.x;
    int tid = threadIdx.x;
    const float* xr = x + (size_t)row * DIMC;
    float4 xv = *(const float4*)(xr + tid * 4);
    float s = xv.x * xv.x + xv.y * xv.y + xv.z * xv.z + xv.w * xv.w;
    #pragma unroll
    for (int off = 16; off; off >>= 1) s += __shfl_xor_sync(0xFFFFFFFFu, s, off);
    __shared__ float ws[8];
    __shared__ float snorm;
    if ((tid & 31) == 0) ws[tid >> 5] = s;
    __syncthreads();
    if (tid == 0) {
        float t = 0.f;
        #pragma unroll
        for (int i = 0; i < 8; i++) t += ws[i];
        snorm = rsqrtf(t * (1.0f / DIMC) + EPSV);
    }
    __syncthreads();
    float n = snorm;
    float4 gv = *(const float4*)(g + tid * 4);
    float4 ov;
    ov.x = xv.x * n * gv.x;
    ov.y = xv.y * n * gv.y;
    ov.z = xv.z * n * gv.z;
    ov.w = xv.w * n * gv.w;
    *(float4*)(y + (size_t)row * DIMC + tid * 4) = ov;
}

// ---------------- TF32 GEMM 128x128, K-chunk 32, ldmatrix, tf32-in-smem -------
// smem stage s: A(tf32) [128 rows][32 k] SW128 at s*16384,
//               B(tf32, n-major) [128 n][32 k] SW128 at 32768 + s*16384
#define GS_A(s) ((s) * 16384)
#define GS_B(s) (32768 + (s) * 16384)
#define G_SMEM  65536
#define SWZ(row, off) ((row) * 128 + ((off) ^ (((row) & 7) << 4)))

__global__ __launch_bounds__(256, 2)
void gemm_tf32(const float* __restrict__ A, const float* __restrict__ B,
               float* __restrict__ C, const float* __restrict__ res,
               int M, int N, int K, int do_silu) {
    extern __shared__ char smc[];
    const uint32_t sbase = smem_u32(smc);
    const int tid = threadIdx.x;
    const int warp = tid >> 5, lane = tid & 31;
    const int lg = lane >> 2, ltg = lane & 3;
    const int wm = warp >> 2, wn = warp & 3;
    const int bm0 = blockIdx.y * 128, bn0 = blockIdx.x * 128;

    // A loader: row = (tid>>3)+32i, k4 = tid&7
    const int a_row = tid >> 3, a_k4 = tid & 7;
    const float* Agp = A + (size_t)(bm0 + a_row) * K + a_k4 * 4;

    // B loader: n = tid&127, k4 = (tid>>7)+2i
    const int b_n = tid & 127, b_k4a = tid >> 7;
    const float* Bgp = B + (size_t)(b_k4a * 4) * N + bn0 + b_n;

    // fragment base addresses (kk=0); per-kk address = base ^ (kk<<5)
    const int mat = lane >> 3, mrow = lane & 7;
    const int ah16 = (mat >> 1) << 4;
    const int bh16 = (mat & 1) << 4;
    int aoff[4], boff[2];
    #pragma unroll
    for (int mt = 0; mt < 4; mt++) {
        int row = wm * 64 + mt * 16 + (mat & 1) * 8 + mrow;
        aoff[mt] = row * 128 + (ah16 ^ ((row & 7) << 4));
    }
    #pragma unroll
    for (int p = 0; p < 2; p++) {
        int n = (wn * 4 + p * 2 + (mat >> 1)) * 8 + mrow;
        boff[p] = n * 128 + (bh16 ^ ((n & 7) << 4));
    }

    float acc[4][4][4];
    #pragma unroll
    for (int mt = 0; mt < 4; mt++)
        #pragma unroll
        for (int nt = 0; nt < 4; nt++)
            #pragma unroll
            for (int r = 0; r < 4; r++) acc[mt][nt][r] = 0.f;

    float ast[4][4];     // A staging
    float bst[4][4];     // B staging

    auto ldgA = [&](int kt) {
        #pragma unroll
        for (int i = 0; i < 4; i++)
            *(float4*)ast[i] = *(const float4*)(Agp + (size_t)i * 32 * K + kt * 32);
    };
    auto ldgB = [&](int kt) {
        #pragma unroll
        for (int i = 0; i < 4; i++) {
            const float* p = Bgp + (size_t)(kt * 32 + i * 8) * N;
            bst[i][0] = p[0];
            bst[i][1] = p[(size_t)N];
            bst[i][2] = p[(size_t)2 * N];
            bst[i][3] = p[(size_t)3 * N];
        }
    };
    auto stsAB = [&](int buf) {
        char* ab = smc + GS_A(buf);
        char* bb = smc + GS_B(buf);
        #pragma unroll
        for (int i = 0; i < 4; i++) {
            int row = a_row + i * 32;
            uint4 u;
            u.x = f2tf(ast[i][0]); u.y = f2tf(ast[i][1]);
            u.z = f2tf(ast[i][2]); u.w = f2tf(ast[i][3]);
            *(uint4*)(ab + SWZ(row, a_k4 * 16)) = u;
        }
        #pragma unroll
        for (int i = 0; i < 4; i++) {
            int k4 = b_k4a + 2 * i;
            uint4 u;
            u.x = f2tf(bst[i][0]); u.y = f2tf(bst[i][1]);
            u.z = f2tf(bst[i][2]); u.w = f2tf(bst[i][3]);
            *(uint4*)(bb + SWZ(b_n, k4 * 16)) = u;
        }
    };

    ldgA(0);
    ldgB(0);
    stsAB(0);
    __syncthreads();

    const int nkt = K >> 5;
    for (int kt = 0; kt < nkt; kt++) {
        int buf = kt & 1;
        bool pf = (kt + 1 < nkt);
        if (pf) {
            ldgA(kt + 1);
            ldgB(kt + 1);
        }
        uint32_t sa = sbase + GS_A(buf);
        uint32_t sb = sbase + GS_B(buf);
        #pragma unroll
        for (int kk = 0; kk < 4; kk++) {
            unsigned af[4][4], bfr[2][4];
            #pragma unroll
            for (int mt = 0; mt < 4; mt++)
                ldsm4(sa + (aoff[mt] ^ (kk << 5)), af[mt]);
            #pragma unroll
            for (int p = 0; p < 2; p++)
                ldsm4(sb + (boff[p] ^ (kk << 5)), bfr[p]);
            #pragma unroll
            for (int mt = 0; mt < 4; mt++)
                #pragma unroll
                for (int nt = 0; nt < 4; nt++)
                    mma8(acc[mt][nt], af[mt], &bfr[nt >> 1][(nt & 1) * 2]);
        }
        if (pf) stsAB(buf ^ 1);
        __syncthreads();
    }

    // epilogue: rows wm*64+mt*16+lg(+8), cols wn*32+nt*8+2*ltg
    #pragma unroll
    for (int mt = 0; mt < 4; mt++) {
        #pragma unroll
        for (int half = 0; half < 2; half++) {
            int r = bm0 + wm * 64 + mt * 16 + lg + half * 8;
            #pragma unroll
            for (int nt = 0; nt < 4; nt++) {
                int c = bn0 + wn * 32 + nt * 8 + 2 * ltg;
                float v0 = acc[mt][nt][half * 2 + 0];
                float v1 = acc[mt][nt][half * 2 + 1];
                if (do_silu) {
                    v0 = v0 / (1.f + __expf(-v0));
                    v1 = v1 / (1.f + __expf(-v1));
                }
                if (res) {
                    float2 rv = *(const float2*)(res + (size_t)r * N + c);
                    v0 += rv.x; v1 += rv.y;
                }
                *(float2*)(C + (size_t)r * N + c) = make_float2(v0, v1);
            }
        }
    }
}

// ---------------- Flash attention (round-2 version) ----------------------------
#define AST 68
#define ATT_SMEM (3 * 64 * AST * 4)

__global__ void attn_tf32(const float* __restrict__ Q, const float* __restrict__ K,
                          const float* __restrict__ V, float* __restrict__ O) {
    extern __shared__ unsigned smu[];
    unsigned* Ks = smu;
    unsigned* Vs = Ks + 64 * AST;
    unsigned* Ps = Vs + 64 * AST;

    int bh = blockIdx.x, qt = blockIdx.y;
    int b = bh >> 4, h = bh & 15;
    int q0 = qt * 64;
    int tid = threadIdx.x, warp = tid >> 5, lane = tid & 31;
    int g = lane >> 2, tg = lane & 3;
    int r0l = warp * 16 + g;

    const float* Qb = Q + ((size_t)(b * TT + q0)) * DIMC + h * HD;
    const float* Kb = K + ((size_t)(b * TT)) * DIMC + h * HD;
    const float* Vb = V + ((size_t)(b * TT)) * DIMC + h * HD;

    unsigned qa[8][4];
    #pragma unroll
    for (int kt = 0; kt < 8; kt++) {
        qa[kt][0] = f2tf(Qb[(size_t)r0l * DIMC + kt * 8 + tg] * 0.125f);
        qa[kt][1] = f2tf(Qb[(size_t)(r0l + 8) * DIMC + kt * 8 + tg] * 0.125f);
        qa[kt][2] = f2tf(Qb[(size_t)r0l * DIMC + kt * 8 + tg + 4] * 0.125f);
        qa[kt][3] = f2tf(Qb[(size_t)(r0l + 8) * DIMC + kt * 8 + tg + 4] * 0.125f);
    }

    float oacc[8][4];
    #pragma unroll
    for (int nt = 0; nt < 8; nt++)
        #pragma unroll
        for (int r = 0; r < 4; r++) oacc[nt][r] = 0.f;
    float m0 = -1e30f, m1 = -1e30f, l0 = 0.f, l1 = 0.f;
    int r0g = q0 + r0l, r1g = r0g + 8;

    for (int s0 = 0; s0 <= q0; s0 += 64) {
        for (int i = tid; i < 1024; i += 128) {
            int r = i >> 4, c = (i & 15) << 2;
            float4 kv = *(const float4*)(Kb + (size_t)(s0 + r) * DIMC + c);
            unsigned* d = &Ks[r * AST + c];
            d[0] = f2tf(kv.x); d[1] = f2tf(kv.y); d[2] = f2tf(kv.z); d[3] = f2tf(kv.w);
            float4 vv = *(const float4*)(Vb + (size_t)(s0 + r) * DIMC + c);
            unsigned* e = &Vs[r * AST + c];
            e[0] = f2tf(vv.x); e[1] = f2tf(vv.y); e[2] = f2tf(vv.z); e[3] = f2tf(vv.w);
        }
        __syncthreads();

        float sc[8][4];
        #pragma unroll
        for (int nt = 0; nt < 8; nt++)
            #pragma unroll
            for (int r = 0; r < 4; r++) sc[nt][r] = 0.f;
        #pragma unroll
        for (int kk = 0; kk < 8; kk++) {
            #pragma unroll
            for (int nt = 0; nt < 8; nt++) {
                unsigned bf[2];
                const unsigned* p = &Ks[(nt * 8 + g) * AST + kk * 8 + tg];
                bf[0] = p[0];
                bf[1] = p[4];
                mma8(sc[nt], qa[kk], bf);
            }
        }

        if (s0 == q0) {
            #pragma unroll
            for (int nt = 0; nt < 8; nt++) {
                int j = s0 + nt * 8 + 2 * tg;
                if (j     > r0g) sc[nt][0] = -1e30f;
                if (j + 1 > r0g) sc[nt][1] = -1e30f;
                if (j     > r1g) sc[nt][2] = -1e30f;
                if (j + 1 > r1g) sc[nt][3] = -1e30f;
            }
        }

        float mx0 = -1e30f, mx1 = -1e30f;
        #pragma unroll
        for (int nt = 0; nt < 8; nt++) {
            mx0 = fmaxf(mx0, fmaxf(sc[nt][0], sc[nt][1]));
            mx1 = fmaxf(mx1, fmaxf(sc[nt][2], sc[nt][3]));
        }
        mx0 = fmaxf(mx0, __shfl_xor_sync(0xFFFFFFFFu, mx0, 1));
        mx0 = fmaxf(mx0, __shfl_xor_sync(0xFFFFFFFFu, mx0, 2));
        mx1 = fmaxf(mx1, __shfl_xor_sync(0xFFFFFFFFu, mx1, 1));
        mx1 = fmaxf(mx1, __shfl_xor_sync(0xFFFFFFFFu, mx1, 2));
        float mn0 = fmaxf(m0, mx0), mn1 = fmaxf(m1, mx1);
        float al0 = __expf(m0 - mn0), al1 = __expf(m1 - mn1);
        float s0r = 0.f, s1r = 0.f;
        #pragma unroll
        for (int nt = 0; nt < 8; nt++) {
            sc[nt][0] = __expf(sc[nt][0] - mn0);
            sc[nt][1] = __expf(sc[nt][1] - mn0);
            sc[nt][2] = __expf(sc[nt][2] - mn1);
            sc[nt][3] = __expf(sc[nt][3] - mn1);
            s0r += sc[nt][0] + sc[nt][1];
            s1r += sc[nt][2] + sc[nt][3];
        }
        s0r += __shfl_xor_sync(0xFFFFFFFFu, s0r, 1);
        s0r += __shfl_xor_sync(0xFFFFFFFFu, s0r, 2);
        s1r += __shfl_xor_sync(0xFFFFFFFFu, s1r, 1);
        s1r += __shfl_xor_sync(0xFFFFFFFFu, s1r, 2);
        l0 = l0 * al0 + s0r;
        l1 = l1 * al1 + s1r;
        m0 = mn0; m1 = mn1;
        #pragma unroll
        for (int nt = 0; nt < 8; nt++) {
            oacc[nt][0] *= al0; oacc[nt][1] *= al0;
            oacc[nt][2] *= al1; oacc[nt][3] *= al1;
        }

        #pragma unroll
        for (int nt = 0; nt < 8; nt++) {
            Ps[r0l * AST + nt * 8 + 2 * tg]           = f2tf(sc[nt][0]);
            Ps[r0l * AST + nt * 8 + 2 * tg + 1]       = f2tf(sc[nt][1]);
            Ps[(r0l + 8) * AST + nt * 8 + 2 * tg]     = f2tf(sc[nt][2]);
            Ps[(r0l + 8) * AST + nt * 8 + 2 * tg + 1] = f2tf(sc[nt][3]);
        }
        __syncwarp();
        unsigned pa[8][4];
        #pragma unroll
        for (int kt = 0; kt < 8; kt++) {
            const unsigned* p = &Ps[r0l * AST + kt * 8 + tg];
            pa[kt][0] = p[0];
            pa[kt][1] = p[8 * AST];
            pa[kt][2] = p[4];
            pa[kt][3] = p[8 * AST + 4];
        }

        #pragma unroll
        for (int kt = 0; kt < 8; kt++) {
            #pragma unroll
            for (int nt = 0; nt < 8; nt++) {
                unsigned bf[2];
                bf[0] = Vs[(kt * 8 + tg) * AST + nt * 8 + g];
                bf[1] = Vs[(kt * 8 + tg + 4) * AST + nt * 8 + g];
                mma8(oacc[nt], pa[kt], bf);
            }
        }
        __syncthreads();
    }

    float il0 = 1.f / l0, il1 = 1.f / l1;
    float* Ob = O + ((size_t)(b * TT + q0 + r0l)) * DIMC + h * HD;
    #pragma unroll
    for (int nt = 0; nt < 8; nt++) {
        *(float2*)(Ob + nt * 8 + 2 * tg) =
            make_float2(oacc[nt][0] * il0, oacc[nt][1] * il0);
        *(float2*)(Ob + (size_t)8 * DIMC + nt * 8 + 2 * tg) =
            make_float2(oacc[nt][2] * il1, oacc[nt][3] * il1);
    }
}

// ---------------- launcher ----------------------------------------------------
extern "C" void kernel_launch(void* const* d_in, const int* in_sizes, int n_in,
                              void* d_out, int out_size) {
    const float* x  = (const float*)d_in[0];
    const float* wq = (const float*)d_in[2];
    const float* wk = (const float*)d_in[3];
    const float* wv = (const float*)d_in[4];
    const float* wo = (const float*)d_in[5];
    const float* w1 = (const float*)d_in[6];
    const float* w2 = (const float*)d_in[7];
    const float* ga = (const float*)d_in[8];
    const float* gf = (const float*)d_in[9];
    float* out = (float*)d_out;

    float *xn, *q, *k, *v, *ao, *x1, *hb;
    cudaGetSymbolAddress((void**)&xn, g_xn);
    cudaGetSymbolAddress((void**)&q,  g_q);
    cudaGetSymbolAddress((void**)&k,  g_k);
    cudaGetSymbolAddress((void**)&v,  g_v);
    cudaGetSymbolAddress((void**)&ao, g_ao);
    cudaGetSymbolAddress((void**)&x1, g_x1);
    cudaGetSymbolAddress((void**)&hb, g_h);

    cudaFuncSetAttribute(gemm_tf32,
                         cudaFuncAttributeMaxDynamicSharedMemorySize, G_SMEM);
    cudaFuncSetAttribute(attn_tf32,
                         cudaFuncAttributeMaxDynamicSharedMemorySize, ATT_SMEM);

    dim3 gN1(DIMC / 128, BT / 128);   // (8, 32)
    dim3 gN4(HID  / 128, BT / 128);   // (32, 32)

    rmsnorm_kernel<<<BT, 256>>>(x, ga, xn);
    gemm_tf32<<<gN1, 256, G_SMEM>>>(xn, wq, q, nullptr, BT, DIMC, DIMC, 0);
    gemm_tf32<<<gN1, 256, G_SMEM>>>(xn, wk, k, nullptr, BT, DIMC, DIMC, 0);
    gemm_tf32<<<gN1, 256, G_SMEM>>>(xn, wv, v, nullptr, BT, DIMC, DIMC, 0);
    attn_tf32<<<dim3(BB * NH, TT / 64), 128, ATT_SMEM>>>(q, k, v, ao);
    gemm_tf32<<<gN1, 256, G_SMEM>>>(ao, wo, x1, x, BT, DIMC, DIMC, 0);
    rmsnorm_kernel<<<BT, 256>>>(x1, gf, xn);
    gemm_tf32<<<gN4, 256, G_SMEM>>>(xn, w1, hb, nullptr, BT, HID, DIMC, 1);
    gemm_tf32<<<gN1, 256, G_SMEM>>>(hb, w2, out, x1, BT, DIMC, HID, 0);
}

// round 7
// speedup vs baseline: 1.2696x; 1.2696x over previous
#include <cuda_runtime.h>
#include <math.h>
#include <cstdint>

#define BB   2
#define TT   2048
#define BT   4096
#define DIMC 1024
#define NH   16
#define HD   64
#define HID  4096
#define EPSV 1e-6f

// ---------------- scratch ----------------------------------------------------
__device__ unsigned g_xn[BT * DIMC];        // rmsnorm out, tf32 bits
__device__ float    g_q [BT * DIMC];
__device__ float    g_k [BT * DIMC];
__device__ float    g_v [BT * DIMC];
__device__ unsigned g_ao[BT * DIMC];        // attn out, tf32 bits
__device__ float    g_x1[BT * DIMC];
__device__ unsigned g_h [BT * HID];         // silu(h@w1), tf32 bits
__device__ unsigned g_wqu[DIMC * DIMC];
__device__ unsigned g_wku[DIMC * DIMC];
__device__ unsigned g_wvu[DIMC * DIMC];
__device__ unsigned g_wou[DIMC * DIMC];
__device__ unsigned g_w1u[DIMC * HID];
__device__ unsigned g_w2u[HID * DIMC];

// ---------------- helpers -----------------------------------------------------
__device__ __forceinline__ unsigned f2tf(float f) {
    unsigned u;
    asm("cvt.rna.tf32.f32 %0, %1;" : "=r"(u) : "f"(f));
    return u;
}
__device__ __forceinline__ uint32_t smem_u32(const void* p) {
    uint32_t a;
    asm("{ .reg .u64 t; cvta.to.shared.u64 t, %1; cvt.u32.u64 %0, t; }"
        : "=r"(a) : "l"(p));
    return a;
}
__device__ __forceinline__ void mma8(float* d, const unsigned* a, const unsigned* b) {
    asm volatile(
        "mma.sync.aligned.m16n8k8.row.col.f32.tf32.tf32.f32 "
        "{%0,%1,%2,%3}, {%4,%5,%6,%7}, {%8,%9}, {%0,%1,%2,%3};"
        : "+f"(d[0]), "+f"(d[1]), "+f"(d[2]), "+f"(d[3])
        : "r"(a[0]), "r"(a[1]), "r"(a[2]), "r"(a[3]), "r"(b[0]), "r"(b[1]));
}
__device__ __forceinline__ void ldsm4(uint32_t addr, unsigned* r) {
    asm volatile("ldmatrix.sync.aligned.m8n8.x4.shared.b16 {%0,%1,%2,%3}, [%4];"
        : "=r"(r[0]), "=r"(r[1]), "=r"(r[2]), "=r"(r[3]) : "r"(addr));
}
__device__ __forceinline__ void cpasync16(uint32_t dst, const void* src) {
    asm volatile("cp.async.cg.shared.global [%0], [%1], 16;"
        :: "r"(dst), "l"(__cvta_generic_to_global(src)));
}
#define CP_COMMIT asm volatile("cp.async.commit_group;" ::: "memory")
#define CP_WAIT0  asm volatile("cp.async.wait_group 0;" ::: "memory")

// ---------------- weight conversion -------------------------------------------
__global__ void cvt_kernel(const float* __restrict__ src,
                           unsigned* __restrict__ dst, int n) {
    int i = (blockIdx.x * blockDim.x + threadIdx.x) * 4;
    if (i < n) {
        float4 v = *(const float4*)(src + i);
        uint4 u;
        u.x = f2tf(v.x); u.y = f2tf(v.y); u.z = f2tf(v.z); u.w = f2tf(v.w);
        *(uint4*)(dst + i) = u;
    }
}

// ---------------- RMSNorm (tf32-bit output) ------------------------------------
__global__ void rmsnorm_kernel(const float* __restrict__ x,
                               const float* __restrict__ g,
                               unsigned* __restrict__ y) {
    int row = blockIdx.x;
    int tid = threadIdx.x;
    const float* xr = x + (size_t)row * DIMC;
    float4 xv = *(const float4*)(xr + tid * 4);
    float s = xv.x * xv.x + xv.y * xv.y + xv.z * xv.z + xv.w * xv.w;
    #pragma unroll
    for (int off = 16; off; off >>= 1) s += __shfl_xor_sync(0xFFFFFFFFu, s, off);
    __shared__ float ws[8];
    __shared__ float snorm;
    if ((tid & 31) == 0) ws[tid >> 5] = s;
    __syncthreads();
    if (tid == 0) {
        float t = 0.f;
        #pragma unroll
        for (int i = 0; i < 8; i++) t += ws[i];
        snorm = rsqrtf(t * (1.0f / DIMC) + EPSV);
    }
    __syncthreads();
    float n = snorm;
    float4 gv = *(const float4*)(g + tid * 4);
    uint4 ov;
    ov.x = f2tf(xv.x * n * gv.x);
    ov.y = f2tf(xv.y * n * gv.y);
    ov.z = f2tf(xv.z * n * gv.z);
    ov.w = f2tf(xv.w * n * gv.w);
    *(uint4*)(y + (size_t)row * DIMC + tid * 4) = ov;
}

// ---------------- TF32 GEMM (pre-converted inputs), 128x128, K-chunk 32 -------
// smem stage s: A [128 rows][32 k] SW128 @ s*16384, B n-major [128 n][32 k] @ 32768+s*16384
#define GS_A(s) ((s) * 16384)
#define GS_B(s) (32768 + (s) * 16384)
#define G_SMEM  65536
#define SWZ(row, off) ((row) * 128 + ((off) ^ (((row) & 7) << 4)))
// mode bits: 1 = silu, 2 = tf32-bit output
__global__ __launch_bounds__(256, 2)
void gemm_tf32(const unsigned* __restrict__ A, const unsigned* __restrict__ B,
               float* __restrict__ C, const float* __restrict__ res,
               int M, int N, int K, int mode) {
    extern __shared__ char smc[];
    const uint32_t sbase = smem_u32(smc);
    const int tid = threadIdx.x;
    const int warp = tid >> 5, lane = tid & 31;
    const int lg = lane >> 2, ltg = lane & 3;
    const int wm = warp >> 2, wn = warp & 3;
    const int bm0 = blockIdx.y * 128, bn0 = blockIdx.x * 128;

    // A loader (cp.async): row = (tid>>3)+32i, k4 = tid&7
    const int a_row = tid >> 3, a_k4 = tid & 7;
    const unsigned* Agp = A + (size_t)(bm0 + a_row) * K + a_k4 * 4;

    // B loader (transpose LDG): n = tid&127, base k4 = tid>>7
    const int b_n = tid & 127, b_k4a = tid >> 7;
    const unsigned* Bgp = B + (size_t)(b_k4a * 4) * N + bn0 + b_n;

    // fragment base addresses (kk=0); per-kk address = base ^ (kk<<5)
    const int mat = lane >> 3, mrow = lane & 7;
    const int ah16 = (mat >> 1) << 4;
    const int bh16 = (mat & 1) << 4;
    int aoff[4], boff[2];
    #pragma unroll
    for (int mt = 0; mt < 4; mt++) {
        int row = wm * 64 + mt * 16 + (mat & 1) * 8 + mrow;
        aoff[mt] = row * 128 + (ah16 ^ ((row & 7) << 4));
    }
    #pragma unroll
    for (int p = 0; p < 2; p++) {
        int n = (wn * 4 + p * 2 + (mat >> 1)) * 8 + mrow;
        boff[p] = n * 128 + (bh16 ^ ((n & 7) << 4));
    }

    float acc[4][4][4];
    #pragma unroll
    for (int mt = 0; mt < 4; mt++)
        #pragma unroll
        for (int nt = 0; nt < 4; nt++)
            #pragma unroll
            for (int r = 0; r < 4; r++) acc[mt][nt][r] = 0.f;

    unsigned bst[4][4];

    auto loadA = [&](int kt, int buf) {
        uint32_t dst = sbase + GS_A(buf);
        #pragma unroll
        for (int i = 0; i < 4; i++) {
            int row = a_row + i * 32;
            cpasync16(dst + SWZ(row, a_k4 * 16), Agp + (size_t)i * 32 * K + kt * 32);
        }
    };
    auto ldgB = [&](int kt) {
        #pragma unroll
        for (int i = 0; i < 4; i++) {
            const unsigned* p = Bgp + (size_t)(kt * 32 + i * 8) * N;
            bst[i][0] = p[0];
            bst[i][1] = p[(size_t)N];
            bst[i][2] = p[(size_t)2 * N];
            bst[i][3] = p[(size_t)3 * N];
        }
    };
    auto stsB = [&](int buf) {
        char* bb = smc + GS_B(buf);
        #pragma unroll
        for (int i = 0; i < 4; i++) {
            int k4 = b_k4a + 2 * i;
            *(uint4*)(bb + SWZ(b_n, k4 * 16)) = *(uint4*)bst[i];
        }
    };

    loadA(0, 0);
    CP_COMMIT;
    ldgB(0);
    stsB(0);
    CP_WAIT0;
    __syncthreads();

    const int nkt = K >> 5;
    for (int kt = 0; kt < nkt; kt++) {
        int buf = kt & 1;
        bool pf = (kt + 1 < nkt);
        if (pf) {
            loadA(kt + 1, buf ^ 1);
            CP_COMMIT;
            ldgB(kt + 1);
        }
        uint32_t sa = sbase + GS_A(buf);
        uint32_t sb = sbase + GS_B(buf);
        #pragma unroll
        for (int kk = 0; kk < 4; kk++) {
            unsigned af[4][4], bfr[2][4];
            #pragma unroll
            for (int mt = 0; mt < 4; mt++)
                ldsm4(sa + (aoff[mt] ^ (kk << 5)), af[mt]);
            #pragma unroll
            for (int p = 0; p < 2; p++)
                ldsm4(sb + (boff[p] ^ (kk << 5)), bfr[p]);
            #pragma unroll
            for (int mt = 0; mt < 4; mt++)
                #pragma unroll
                for (int nt = 0; nt < 4; nt++)
                    mma8(acc[mt][nt], af[mt], &bfr[nt >> 1][(nt & 1) * 2]);
        }
        if (pf) {
            stsB(buf ^ 1);
            CP_WAIT0;
        }
        __syncthreads();
    }

    // epilogue: rows wm*64+mt*16+lg(+8), cols wn*32+nt*8+2*ltg
    #pragma unroll
    for (int mt = 0; mt < 4; mt++) {
        #pragma unroll
        for (int half = 0; half < 2; half++) {
            int r = bm0 + wm * 64 + mt * 16 + lg + half * 8;
            #pragma unroll
            for (int nt = 0; nt < 4; nt++) {
                int c = bn0 + wn * 32 + nt * 8 + 2 * ltg;
                float v0 = acc[mt][nt][half * 2 + 0];
                float v1 = acc[mt][nt][half * 2 + 1];
                if (mode & 1) {
                    v0 = v0 / (1.f + __expf(-v0));
                    v1 = v1 / (1.f + __expf(-v1));
                }
                if (res) {
                    float2 rv = *(const float2*)(res + (size_t)r * N + c);
                    v0 += rv.x; v1 += rv.y;
                }
                if (mode & 2) {
                    uint2 u; u.x = f2tf(v0); u.y = f2tf(v1);
                    *(uint2*)((unsigned*)C + (size_t)r * N + c) = u;
                } else {
                    *(float2*)(C + (size_t)r * N + c) = make_float2(v0, v1);
                }
            }
        }
    }
}

// ---------------- Flash attention (tf32-bit output) ----------------------------
#define AST 68
#define ATT_SMEM (3 * 64 * AST * 4)

__global__ void attn_tf32(const float* __restrict__ Q, const float* __restrict__ K,
                          const float* __restrict__ V, unsigned* __restrict__ O) {
    extern __shared__ unsigned smu[];
    unsigned* Ks = smu;
    unsigned* Vs = Ks + 64 * AST;
    unsigned* Ps = Vs + 64 * AST;

    int bh = blockIdx.x, qt = blockIdx.y;
    int b = bh >> 4, h = bh & 15;
    int q0 = qt * 64;
    int tid = threadIdx.x, warp = tid >> 5, lane = tid & 31;
    int g = lane >> 2, tg = lane & 3;
    int r0l = warp * 16 + g;

    const float* Qb = Q + ((size_t)(b * TT + q0)) * DIMC + h * HD;
    const float* Kb = K + ((size_t)(b * TT)) * DIMC + h * HD;
    const float* Vb = V + ((size_t)(b * TT)) * DIMC + h * HD;

    unsigned qa[8][4];
    #pragma unroll
    for (int kt = 0; kt < 8; kt++) {
        qa[kt][0] = f2tf(Qb[(size_t)r0l * DIMC + kt * 8 + tg] * 0.125f);
        qa[kt][1] = f2tf(Qb[(size_t)(r0l + 8) * DIMC + kt * 8 + tg] * 0.125f);
        qa[kt][2] = f2tf(Qb[(size_t)r0l * DIMC + kt * 8 + tg + 4] * 0.125f);
        qa[kt][3] = f2tf(Qb[(size_t)(r0l + 8) * DIMC + kt * 8 + tg + 4] * 0.125f);
    }

    float oacc[8][4];
    #pragma unroll
    for (int nt = 0; nt < 8; nt++)
        #pragma unroll
        for (int r = 0; r < 4; r++) oacc[nt][r] = 0.f;
    float m0 = -1e30f, m1 = -1e30f, l0 = 0.f, l1 = 0.f;
    int r0g = q0 + r0l, r1g = r0g + 8;

    for (int s0 = 0; s0 <= q0; s0 += 64) {
        for (int i = tid; i < 1024; i += 128) {
            int r = i >> 4, c = (i & 15) << 2;
            float4 kv = *(const float4*)(Kb + (size_t)(s0 + r) * DIMC + c);
            unsigned* d = &Ks[r * AST + c];
            d[0] = f2tf(kv.x); d[1] = f2tf(kv.y); d[2] = f2tf(kv.z); d[3] = f2tf(kv.w);
            float4 vv = *(const float4*)(Vb + (size_t)(s0 + r) * DIMC + c);
            unsigned* e = &Vs[r * AST + c];
            e[0] = f2tf(vv.x); e[1] = f2tf(vv.y); e[2] = f2tf(vv.z); e[3] = f2tf(vv.w);
        }
        __syncthreads();

        float sc[8][4];
        #pragma unroll
        for (int nt = 0; nt < 8; nt++)
            #pragma unroll
            for (int r = 0; r < 4; r++) sc[nt][r] = 0.f;
        #pragma unroll
        for (int kk = 0; kk < 8; kk++) {
            #pragma unroll
            for (int nt = 0; nt < 8; nt++) {
                unsigned bf[2];
                const unsigned* p = &Ks[(nt * 8 + g) * AST + kk * 8 + tg];
                bf[0] = p[0];
                bf[1] = p[4];
                mma8(sc[nt], qa[kk], bf);
            }
        }

        if (s0 == q0) {
            #pragma unroll
            for (int nt = 0; nt < 8; nt++) {
                int j = s0 + nt * 8 + 2 * tg;
                if (j     > r0g) sc[nt][0] = -1e30f;
                if (j + 1 > r0g) sc[nt][1] = -1e30f;
                if (j     > r1g) sc[nt][2] = -1e30f;
                if (j + 1 > r1g) sc[nt][3] = -1e30f;
            }
        }

        float mx0 = -1e30f, mx1 = -1e30f;
        #pragma unroll
        for (int nt = 0; nt < 8; nt++) {
            mx0 = fmaxf(mx0, fmaxf(sc[nt][0], sc[nt][1]));
            mx1 = fmaxf(mx1, fmaxf(sc[nt][2], sc[nt][3]));
        }
        mx0 = fmaxf(mx0, __shfl_xor_sync(0xFFFFFFFFu, mx0, 1));
        mx0 = fmaxf(mx0, __shfl_xor_sync(0xFFFFFFFFu, mx0, 2));
        mx1 = fmaxf(mx1, __shfl_xor_sync(0xFFFFFFFFu, mx1, 1));
        mx1 = fmaxf(mx1, __shfl_xor_sync(0xFFFFFFFFu, mx1, 2));
        float mn0 = fmaxf(m0, mx0), mn1 = fmaxf(m1, mx1);
        float al0 = __expf(m0 - mn0), al1 = __expf(m1 - mn1);
        float s0r = 0.f, s1r = 0.f;
        #pragma unroll
        for (int nt = 0; nt < 8; nt++) {
            sc[nt][0] = __expf(sc[nt][0] - mn0);
            sc[nt][1] = __expf(sc[nt][1] - mn0);
            sc[nt][2] = __expf(sc[nt][2] - mn1);
            sc[nt][3] = __expf(sc[nt][3] - mn1);
            s0r += sc[nt][0] + sc[nt][1];
            s1r += sc[nt][2] + sc[nt][3];
        }
        s0r += __shfl_xor_sync(0xFFFFFFFFu, s0r, 1);
        s0r += __shfl_xor_sync(0xFFFFFFFFu, s0r, 2);
        s1r += __shfl_xor_sync(0xFFFFFFFFu, s1r, 1);
        s1r += __shfl_xor_sync(0xFFFFFFFFu, s1r, 2);
        l0 = l0 * al0 + s0r;
        l1 = l1 * al1 + s1r;
        m0 = mn0; m1 = mn1;
        #pragma unroll
        for (int nt = 0; nt < 8; nt++) {
            oacc[nt][0] *= al0; oacc[nt][1] *= al0;
            oacc[nt][2] *= al1; oacc[nt][3] *= al1;
        }

        #pragma unroll
        for (int nt = 0; nt < 8; nt++) {
            Ps[r0l * AST + nt * 8 + 2 * tg]           = f2tf(sc[nt][0]);
            Ps[r0l * AST + nt * 8 + 2 * tg + 1]       = f2tf(sc[nt][1]);
            Ps[(r0l + 8) * AST + nt * 8 + 2 * tg]     = f2tf(sc[nt][2]);
            Ps[(r0l + 8) * AST + nt * 8 + 2 * tg + 1] = f2tf(sc[nt][3]);
        }
        __syncwarp();
        unsigned pa[8][4];
        #pragma unroll
        for (int kt = 0; kt < 8; kt++) {
            const unsigned* p = &Ps[r0l * AST + kt * 8 + tg];
            pa[kt][0] = p[0];
            pa[kt][1] = p[8 * AST];
            pa[kt][2] = p[4];
            pa[kt][3] = p[8 * AST + 4];
        }

        #pragma unroll
        for (int kt = 0; kt < 8; kt++) {
            #pragma unroll
            for (int nt = 0; nt < 8; nt++) {
                unsigned bf[2];
                bf[0] = Vs[(kt * 8 + tg) * AST + nt * 8 + g];
                bf[1] = Vs[(kt * 8 + tg + 4) * AST + nt * 8 + g];
                mma8(oacc[nt], pa[kt], bf);
            }
        }
        __syncthreads();
    }

    float il0 = 1.f / l0, il1 = 1.f / l1;
    unsigned* Ob = O + ((size_t)(b * TT + q0 + r0l)) * DIMC + h * HD;
    #pragma unroll
    for (int nt = 0; nt < 8; nt++) {
        uint2 u0, u1;
        u0.x = f2tf(oacc[nt][0] * il0); u0.y = f2tf(oacc[nt][1] * il0);
        u1.x = f2tf(oacc[nt][2] * il1); u1.y = f2tf(oacc[nt][3] * il1);
        *(uint2*)(Ob + nt * 8 + 2 * tg) = u0;
        *(uint2*)(Ob + (size_t)8 * DIMC + nt * 8 + 2 * tg) = u1;
    }
}

// ---------------- launcher ----------------------------------------------------
extern "C" void kernel_launch(void* const* d_in, const int* in_sizes, int n_in,
                              void* d_out, int out_size) {
    const float* x  = (const float*)d_in[0];
    const float* wq = (const float*)d_in[2];
    const float* wk = (const float*)d_in[3];
    const float* wv = (const float*)d_in[4];
    const float* wo = (const float*)d_in[5];
    const float* w1 = (const float*)d_in[6];
    const float* w2 = (const float*)d_in[7];
    const float* ga = (const float*)d_in[8];
    const float* gf = (const float*)d_in[9];
    float* out = (float*)d_out;

    unsigned *xn, *ao, *hb, *wqu, *wku, *wvu, *wou, *w1u, *w2u;
    float *q, *k, *v, *x1;
    cudaGetSymbolAddress((void**)&xn,  g_xn);
    cudaGetSymbolAddress((void**)&q,   g_q);
    cudaGetSymbolAddress((void**)&k,   g_k);
    cudaGetSymbolAddress((void**)&v,   g_v);
    cudaGetSymbolAddress((void**)&ao,  g_ao);
    cudaGetSymbolAddress((void**)&x1,  g_x1);
    cudaGetSymbolAddress((void**)&hb,  g_h);
    cudaGetSymbolAddress((void**)&wqu, g_wqu);
    cudaGetSymbolAddress((void**)&wku, g_wku);
    cudaGetSymbolAddress((void**)&wvu, g_wvu);
    cudaGetSymbolAddress((void**)&wou, g_wou);
    cudaGetSymbolAddress((void**)&w1u, g_w1u);
    cudaGetSymbolAddress((void**)&w2u, g_w2u);

    cudaFuncSetAttribute(gemm_tf32,
                         cudaFuncAttributeMaxDynamicSharedMemorySize, G_SMEM);
    cudaFuncSetAttribute(attn_tf32,
                         cudaFuncAttributeMaxDynamicSharedMemorySize, ATT_SMEM);

    const int nW = DIMC * DIMC, nW4 = DIMC * HID;
    cvt_kernel<<<nW / 1024, 256>>>(wq, wqu, nW);
    cvt_kernel<<<nW / 1024, 256>>>(wk, wku, nW);
    cvt_kernel<<<nW / 1024, 256>>>(wv, wvu, nW);
    cvt_kernel<<<nW / 1024, 256>>>(wo, wou, nW);
    cvt_kernel<<<nW4 / 1024, 256>>>(w1, w1u, nW4);
    cvt_kernel<<<nW4 / 1024, 256>>>(w2, w2u, nW4);

    dim3 gN1(DIMC / 128, BT / 128);   // (8, 32)
    dim3 gN4(HID  / 128, BT / 128);   // (32, 32)

    rmsnorm_kernel<<<BT, 256>>>(x, ga, xn);
    gemm_tf32<<<gN1, 256, G_SMEM>>>(xn, wqu, q, nullptr, BT, DIMC, DIMC, 0);
    gemm_tf32<<<gN1, 256, G_SMEM>>>(xn, wku, k, nullptr, BT, DIMC, DIMC, 0);
    gemm_tf32<<<gN1, 256, G_SMEM>>>(xn, wvu, v, nullptr, BT, DIMC, DIMC, 0);
    attn_tf32<<<dim3(BB * NH, TT / 64), 128, ATT_SMEM>>>(q, k, v, ao);
    gemm_tf32<<<gN1, 256, G_SMEM>>>(ao, wou, x1, x, BT, DIMC, DIMC, 0);
    rmsnorm_kernel<<<BT, 256>>>(x1, gf, xn);
    gemm_tf32<<<gN4, 256, G_SMEM>>>(xn, w1u, (float*)hb, nullptr, BT, HID, DIMC, 3);
    gemm_tf32<<<gN1, 256, G_SMEM>>>(hb, w2u, out, x1, BT, DIMC, HID, 0);
}

// round 8
// speedup vs baseline: 1.2727x; 1.0024x over previous
#include <cuda_runtime.h>
#include <math.h>
#include <cstdint>

#define BB   2
#define TT   2048
#define BT   4096
#define DIMC 1024
#define NH   16
#define HD   64
#define HID  4096
#define QKVD 3072
#define EPSV 1e-6f

// ---------------- scratch ----------------------------------------------------
__device__ unsigned g_xn  [BT * DIMC];       // rmsnorm out, tf32 bits
__device__ unsigned g_qkv [BT * QKVD];       // fused qkv, tf32 bits
__device__ unsigned g_ao  [BT * DIMC];       // attn out, tf32 bits
__device__ float    g_x1  [BT * DIMC];
__device__ unsigned g_h   [BT * HID];        // silu(h@w1), tf32 bits
__device__ unsigned g_wqkv[DIMC * QKVD];     // packed wq|wk|wv (wq pre-scaled 1/8)
__device__ unsigned g_wou [DIMC * DIMC];
__device__ unsigned g_w1u [DIMC * HID];
__device__ unsigned g_w2u [HID * DIMC];

// ---------------- helpers -----------------------------------------------------
__device__ __forceinline__ unsigned f2tf(float f) {
    unsigned u;
    asm("cvt.rna.tf32.f32 %0, %1;" : "=r"(u) : "f"(f));
    return u;
}
__device__ __forceinline__ uint32_t smem_u32(const void* p) {
    uint32_t a;
    asm("{ .reg .u64 t; cvta.to.shared.u64 t, %1; cvt.u32.u64 %0, t; }"
        : "=r"(a) : "l"(p));
    return a;
}
__device__ __forceinline__ void mma8(float* d, const unsigned* a, const unsigned* b) {
    asm volatile(
        "mma.sync.aligned.m16n8k8.row.col.f32.tf32.tf32.f32 "
        "{%0,%1,%2,%3}, {%4,%5,%6,%7}, {%8,%9}, {%0,%1,%2,%3};"
        : "+f"(d[0]), "+f"(d[1]), "+f"(d[2]), "+f"(d[3])
        : "r"(a[0]), "r"(a[1]), "r"(a[2]), "r"(a[3]), "r"(b[0]), "r"(b[1]));
}
__device__ __forceinline__ void ldsm4(uint32_t addr, unsigned* r) {
    asm volatile("ldmatrix.sync.aligned.m8n8.x4.shared.b16 {%0,%1,%2,%3}, [%4];"
        : "=r"(r[0]), "=r"(r[1]), "=r"(r[2]), "=r"(r[3]) : "r"(addr));
}
__device__ __forceinline__ void cpasync16(uint32_t dst, const void* src) {
    asm volatile("cp.async.cg.shared.global [%0], [%1], 16;"
        :: "r"(dst), "l"(__cvta_generic_to_global(src)));
}
#define CP_COMMIT asm volatile("cp.async.commit_group;" ::: "memory")
#define CP_WAIT0  asm volatile("cp.async.wait_group 0;" ::: "memory")

// ---------------- weight conversion / packing ----------------------------------
__global__ void cvt_kernel(const float* __restrict__ src,
                           unsigned* __restrict__ dst, int n) {
    int i = (blockIdx.x * blockDim.x + threadIdx.x) * 4;
    if (i < n) {
        float4 v = *(const float4*)(src + i);
        uint4 u;
        u.x = f2tf(v.x); u.y = f2tf(v.y); u.z = f2tf(v.z); u.w = f2tf(v.w);
        *(uint4*)(dst + i) = u;
    }
}
// pack one [DIMC,DIMC] matrix into g_wqkv at column offset `coff`, scaled
__global__ void pack_qkv_kernel(const float* __restrict__ src,
                                unsigned* __restrict__ dst, int coff, float scale) {
    int i = (blockIdx.x * blockDim.x + threadIdx.x) * 4;   // i < DIMC*DIMC
    int r = i >> 10, c = i & 1023;
    float4 v = *(const float4*)(src + i);
    uint4 u;
    u.x = f2tf(v.x * scale); u.y = f2tf(v.y * scale);
    u.z = f2tf(v.z * scale); u.w = f2tf(v.w * scale);
    *(uint4*)(dst + (size_t)r * QKVD + coff + c) = u;
}

// ---------------- RMSNorm (tf32-bit output) ------------------------------------
__global__ void rmsnorm_kernel(const float* __restrict__ x,
                               const float* __restrict__ g,
                               unsigned* __restrict__ y) {
    int row = blockIdx.x;
    int tid = threadIdx.x;
    const float* xr = x + (size_t)row * DIMC;
    float4 xv = *(const float4*)(xr + tid * 4);
    float s = xv.x * xv.x + xv.y * xv.y + xv.z * xv.z + xv.w * xv.w;
    #pragma unroll
    for (int off = 16; off; off >>= 1) s += __shfl_xor_sync(0xFFFFFFFFu, s, off);
    __shared__ float ws[8];
    __shared__ float snorm;
    if ((tid & 31) == 0) ws[tid >> 5] = s;
    __syncthreads();
    if (tid == 0) {
        float t = 0.f;
        #pragma unroll
        for (int i = 0; i < 8; i++) t += ws[i];
        snorm = rsqrtf(t * (1.0f / DIMC) + EPSV);
    }
    __syncthreads();
    float n = snorm;
    float4 gv = *(const float4*)(g + tid * 4);
    uint4 ov;
    ov.x = f2tf(xv.x * n * gv.x);
    ov.y = f2tf(xv.y * n * gv.y);
    ov.z = f2tf(xv.z * n * gv.z);
    ov.w = f2tf(xv.w * n * gv.w);
    *(uint4*)(y + (size_t)row * DIMC + tid * 4) = ov;
}

// ---------------- TF32 GEMM (pre-converted inputs), 128x128, K-chunk 32 -------
#define GS_A(s) ((s) * 16384)
#define GS_B(s) (32768 + (s) * 16384)
#define G_SMEM  65536
#define SWZ(row, off) ((row) * 128 + ((off) ^ (((row) & 7) << 4)))
// mode bits: 1 = silu, 2 = tf32-bit output
__global__ __launch_bounds__(256, 2)
void gemm_tf32(const unsigned* __restrict__ A, const unsigned* __restrict__ B,
               float* __restrict__ C, const float* __restrict__ res,
               int M, int N, int K, int mode) {
    extern __shared__ char smc[];
    const uint32_t sbase = smem_u32(smc);
    const int tid = threadIdx.x;
    const int warp = tid >> 5, lane = tid & 31;
    const int lg = lane >> 2, ltg = lane & 3;
    const int wm = warp >> 2, wn = warp & 3;
    const int bm0 = blockIdx.y * 128, bn0 = blockIdx.x * 128;

    const int a_row = tid >> 3, a_k4 = tid & 7;
    const unsigned* Agp = A + (size_t)(bm0 + a_row) * K + a_k4 * 4;

    const int b_n = tid & 127, b_k4a = tid >> 7;
    const unsigned* Bgp = B + (size_t)(b_k4a * 4) * N + bn0 + b_n;

    const int mat = lane >> 3, mrow = lane & 7;
    const int ah16 = (mat >> 1) << 4;
    const int bh16 = (mat & 1) << 4;
    int aoff[4], boff[2];
    #pragma unroll
    for (int mt = 0; mt < 4; mt++) {
        int row = wm * 64 + mt * 16 + (mat & 1) * 8 + mrow;
        aoff[mt] = row * 128 + (ah16 ^ ((row & 7) << 4));
    }
    #pragma unroll
    for (int p = 0; p < 2; p++) {
        int n = (wn * 4 + p * 2 + (mat >> 1)) * 8 + mrow;
        boff[p] = n * 128 + (bh16 ^ ((n & 7) << 4));
    }

    float acc[4][4][4];
    #pragma unroll
    for (int mt = 0; mt < 4; mt++)
        #pragma unroll
        for (int nt = 0; nt < 4; nt++)
            #pragma unroll
            for (int r = 0; r < 4; r++) acc[mt][nt][r] = 0.f;

    unsigned bst[4][4];

    auto loadA = [&](int kt, int buf) {
        uint32_t dst = sbase + GS_A(buf);
        #pragma unroll
        for (int i = 0; i < 4; i++) {
            int row = a_row + i * 32;
            cpasync16(dst + SWZ(row, a_k4 * 16), Agp + (size_t)i * 32 * K + kt * 32);
        }
    };
    auto ldgB = [&](int kt) {
        #pragma unroll
        for (int i = 0; i < 4; i++) {
            const unsigned* p = Bgp + (size_t)(kt * 32 + i * 8) * N;
            bst[i][0] = p[0];
            bst[i][1] = p[(size_t)N];
            bst[i][2] = p[(size_t)2 * N];
            bst[i][3] = p[(size_t)3 * N];
        }
    };
    auto stsB = [&](int buf) {
        char* bb = smc + GS_B(buf);
        #pragma unroll
        for (int i = 0; i < 4; i++) {
            int k4 = b_k4a + 2 * i;
            *(uint4*)(bb + SWZ(b_n, k4 * 16)) = *(uint4*)bst[i];
        }
    };

    loadA(0, 0);
    CP_COMMIT;
    ldgB(0);
    stsB(0);
    CP_WAIT0;
    __syncthreads();

    const int nkt = K >> 5;
    for (int kt = 0; kt < nkt; kt++) {
        int buf = kt & 1;
        bool pf = (kt + 1 < nkt);
        if (pf) {
            loadA(kt + 1, buf ^ 1);
            CP_COMMIT;
            ldgB(kt + 1);
        }
        uint32_t sa = sbase + GS_A(buf);
        uint32_t sb = sbase + GS_B(buf);
        #pragma unroll
        for (int kk = 0; kk < 4; kk++) {
            unsigned af[4][4], bfr[2][4];
            #pragma unroll
            for (int mt = 0; mt < 4; mt++)
                ldsm4(sa + (aoff[mt] ^ (kk << 5)), af[mt]);
            #pragma unroll
            for (int p = 0; p < 2; p++)
                ldsm4(sb + (boff[p] ^ (kk << 5)), bfr[p]);
            #pragma unroll
            for (int mt = 0; mt < 4; mt++)
                #pragma unroll
                for (int nt = 0; nt < 4; nt++)
                    mma8(acc[mt][nt], af[mt], &bfr[nt >> 1][(nt & 1) * 2]);
        }
        if (pf) {
            stsB(buf ^ 1);
            CP_WAIT0;
        }
        __syncthreads();
    }

    #pragma unroll
    for (int mt = 0; mt < 4; mt++) {
        #pragma unroll
        for (int half = 0; half < 2; half++) {
            int r = bm0 + wm * 64 + mt * 16 + lg + half * 8;
            #pragma unroll
            for (int nt = 0; nt < 4; nt++) {
                int c = bn0 + wn * 32 + nt * 8 + 2 * ltg;
                float v0 = acc[mt][nt][half * 2 + 0];
                float v1 = acc[mt][nt][half * 2 + 1];
                if (mode & 1) {
                    v0 = v0 / (1.f + __expf(-v0));
                    v1 = v1 / (1.f + __expf(-v1));
                }
                if (res) {
                    float2 rv = *(const float2*)(res + (size_t)r * N + c);
                    v0 += rv.x; v1 += rv.y;
                }
                if (mode & 2) {
                    uint2 u; u.x = f2tf(v0); u.y = f2tf(v1);
                    *(uint2*)((unsigned*)C + (size_t)r * N + c) = u;
                } else {
                    *(float2*)(C + (size_t)r * N + c) = make_float2(v0, v1);
                }
            }
        }
    }
}

// ---------------- Flash attention (bit inputs, bit output) ---------------------
#define AST 68
#define ATT_SMEM (3 * 64 * AST * 4)

__global__ void attn_tf32(const unsigned* __restrict__ QKV,
                          unsigned* __restrict__ O) {
    extern __shared__ unsigned smu[];
    unsigned* Ks = smu;
    unsigned* Vs = Ks + 64 * AST;
    unsigned* Ps = Vs + 64 * AST;

    int bh = blockIdx.x, qt = blockIdx.y;
    int b = bh >> 4, h = bh & 15;
    int q0 = qt * 64;
    int tid = threadIdx.x, warp = tid >> 5, lane = tid & 31;
    int g = lane >> 2, tg = lane & 3;
    int r0l = warp * 16 + g;

    const unsigned* Qb = QKV + ((size_t)(b * TT + q0)) * QKVD + h * HD;
    const unsigned* Kb = QKV + ((size_t)(b * TT)) * QKVD + DIMC + h * HD;
    const unsigned* Vb = QKV + ((size_t)(b * TT)) * QKVD + 2 * DIMC + h * HD;

    // Q fragments: raw tf32 bits (wq pre-scaled by 1/8 at pack time)
    unsigned qa[8][4];
    #pragma unroll
    for (int kt = 0; kt < 8; kt++) {
        qa[kt][0] = Qb[(size_t)r0l * QKVD + kt * 8 + tg];
        qa[kt][1] = Qb[(size_t)(r0l + 8) * QKVD + kt * 8 + tg];
        qa[kt][2] = Qb[(size_t)r0l * QKVD + kt * 8 + tg + 4];
        qa[kt][3] = Qb[(size_t)(r0l + 8) * QKVD + kt * 8 + tg + 4];
    }

    float oacc[8][4];
    #pragma unroll
    for (int nt = 0; nt < 8; nt++)
        #pragma unroll
        for (int r = 0; r < 4; r++) oacc[nt][r] = 0.f;
    float m0 = -1e30f, m1 = -1e30f, l0 = 0.f, l1 = 0.f;
    int r0g = q0 + r0l, r1g = r0g + 8;

    for (int s0 = 0; s0 <= q0; s0 += 64) {
        // K/V tile: raw bit copy, no conversion
        for (int i = tid; i < 1024; i += 128) {
            int r = i >> 4, c = (i & 15) << 2;
            *(uint4*)&Ks[r * AST + c] =
                *(const uint4*)(Kb + (size_t)(s0 + r) * QKVD + c);
            *(uint4*)&Vs[r * AST + c] =
                *(const uint4*)(Vb + (size_t)(s0 + r) * QKVD + c);
        }
        __syncthreads();

        float sc[8][4];
        #pragma unroll
        for (int nt = 0; nt < 8; nt++)
            #pragma unroll
            for (int r = 0; r < 4; r++) sc[nt][r] = 0.f;
        #pragma unroll
        for (int kk = 0; kk < 8; kk++) {
            #pragma unroll
            for (int nt = 0; nt < 8; nt++) {
                unsigned bf[2];
                const unsigned* p = &Ks[(nt * 8 + g) * AST + kk * 8 + tg];
                bf[0] = p[0];
                bf[1] = p[4];
                mma8(sc[nt], qa[kk], bf);
            }
        }

        if (s0 == q0) {
            #pragma unroll
            for (int nt = 0; nt < 8; nt++) {
                int j = s0 + nt * 8 + 2 * tg;
                if (j     > r0g) sc[nt][0] = -1e30f;
                if (j + 1 > r0g) sc[nt][1] = -1e30f;
                if (j     > r1g) sc[nt][2] = -1e30f;
                if (j + 1 > r1g) sc[nt][3] = -1e30f;
            }
        }

        float mx0 = -1e30f, mx1 = -1e30f;
        #pragma unroll
        for (int nt = 0; nt < 8; nt++) {
            mx0 = fmaxf(mx0, fmaxf(sc[nt][0], sc[nt][1]));
            mx1 = fmaxf(mx1, fmaxf(sc[nt][2], sc[nt][3]));
        }
        mx0 = fmaxf(mx0, __shfl_xor_sync(0xFFFFFFFFu, mx0, 1));
        mx0 = fmaxf(mx0, __shfl_xor_sync(0xFFFFFFFFu, mx0, 2));
        mx1 = fmaxf(mx1, __shfl_xor_sync(0xFFFFFFFFu, mx1, 1));
        mx1 = fmaxf(mx1, __shfl_xor_sync(0xFFFFFFFFu, mx1, 2));
        float mn0 = fmaxf(m0, mx0), mn1 = fmaxf(m1, mx1);
        float al0 = __expf(m0 - mn0), al1 = __expf(m1 - mn1);
        float s0r = 0.f, s1r = 0.f;
        #pragma unroll
        for (int nt = 0; nt < 8; nt++) {
            sc[nt][0] = __expf(sc[nt][0] - mn0);
            sc[nt][1] = __expf(sc[nt][1] - mn0);
            sc[nt][2] = __expf(sc[nt][2] - mn1);
            sc[nt][3] = __expf(sc[nt][3] - mn1);
            s0r += sc[nt][0] + sc[nt][1];
            s1r += sc[nt][2] + sc[nt][3];
        }
        s0r += __shfl_xor_sync(0xFFFFFFFFu, s0r, 1);
        s0r += __shfl_xor_sync(0xFFFFFFFFu, s0r, 2);
        s1r += __shfl_xor_sync(0xFFFFFFFFu, s1r, 1);
        s1r += __shfl_xor_sync(0xFFFFFFFFu, s1r, 2);
        l0 = l0 * al0 + s0r;
        l1 = l1 * al1 + s1r;
        m0 = mn0; m1 = mn1;
        #pragma unroll
        for (int nt = 0; nt < 8; nt++) {
            oacc[nt][0] *= al0; oacc[nt][1] *= al0;
            oacc[nt][2] *= al1; oacc[nt][3] *= al1;
        }

        #pragma unroll
        for (int nt = 0; nt < 8; nt++) {
            Ps[r0l * AST + nt * 8 + 2 * tg]           = f2tf(sc[nt][0]);
            Ps[r0l * AST + nt * 8 + 2 * tg + 1]       = f2tf(sc[nt][1]);
            Ps[(r0l + 8) * AST + nt * 8 + 2 * tg]     = f2tf(sc[nt][2]);
            Ps[(r0l + 8) * AST + nt * 8 + 2 * tg + 1] = f2tf(sc[nt][3]);
        }
        __syncwarp();
        unsigned pa[8][4];
        #pragma unroll
        for (int kt = 0; kt < 8; kt++) {
            const unsigned* p = &Ps[r0l * AST + kt * 8 + tg];
            pa[kt][0] = p[0];
            pa[kt][1] = p[8 * AST];
            pa[kt][2] = p[4];
            pa[kt][3] = p[8 * AST + 4];
        }

        #pragma unroll
        for (int kt = 0; kt < 8; kt++) {
            #pragma unroll
            for (int nt = 0; nt < 8; nt++) {
                unsigned bf[2];
                bf[0] = Vs[(kt * 8 + tg) * AST + nt * 8 + g];
                bf[1] = Vs[(kt * 8 + tg + 4) * AST + nt * 8 + g];
                mma8(oacc[nt], pa[kt], bf);
            }
        }
        __syncthreads();
    }

    float il0 = 1.f / l0, il1 = 1.f / l1;
    unsigned* Ob = O + ((size_t)(b * TT + q0 + r0l)) * DIMC + h * HD;
    #pragma unroll
    for (int nt = 0; nt < 8; nt++) {
        uint2 u0, u1;
        u0.x = f2tf(oacc[nt][0] * il0); u0.y = f2tf(oacc[nt][1] * il0);
        u1.x = f2tf(oacc[nt][2] * il1); u1.y = f2tf(oacc[nt][3] * il1);
        *(uint2*)(Ob + nt * 8 + 2 * tg) = u0;
        *(uint2*)(Ob + (size_t)8 * DIMC + nt * 8 + 2 * tg) = u1;
    }
}

// ---------------- launcher ----------------------------------------------------
extern "C" void kernel_launch(void* const* d_in, const int* in_sizes, int n_in,
                              void* d_out, int out_size) {
    const float* x  = (const float*)d_in[0];
    const float* wq = (const float*)d_in[2];
    const float* wk = (const float*)d_in[3];
    const float* wv = (const float*)d_in[4];
    const float* wo = (const float*)d_in[5];
    const float* w1 = (const float*)d_in[6];
    const float* w2 = (const float*)d_in[7];
    const float* ga = (const float*)d_in[8];
    const float* gf = (const float*)d_in[9];
    float* out = (float*)d_out;

    unsigned *xn, *qkv, *ao, *hb, *wqkv, *wou, *w1u, *w2u;
    float *x1;
    cudaGetSymbolAddress((void**)&xn,   g_xn);
    cudaGetSymbolAddress((void**)&qkv,  g_qkv);
    cudaGetSymbolAddress((void**)&ao,   g_ao);
    cudaGetSymbolAddress((void**)&x1,   g_x1);
    cudaGetSymbolAddress((void**)&hb,   g_h);
    cudaGetSymbolAddress((void**)&wqkv, g_wqkv);
    cudaGetSymbolAddress((void**)&wou,  g_wou);
    cudaGetSymbolAddress((void**)&w1u,  g_w1u);
    cudaGetSymbolAddress((void**)&w2u,  g_w2u);

    cudaFuncSetAttribute(gemm_tf32,
                         cudaFuncAttributeMaxDynamicSharedMemorySize, G_SMEM);
    cudaFuncSetAttribute(attn_tf32,
                         cudaFuncAttributeMaxDynamicSharedMemorySize, ATT_SMEM);

    const int nW = DIMC * DIMC, nW4 = DIMC * HID;
    pack_qkv_kernel<<<nW / 1024, 256>>>(wq, wqkv, 0,        0.125f);
    pack_qkv_kernel<<<nW / 1024, 256>>>(wk, wqkv, DIMC,     1.0f);
    pack_qkv_kernel<<<nW / 1024, 256>>>(wv, wqkv, 2 * DIMC, 1.0f);
    cvt_kernel<<<nW / 1024, 256>>>(wo, wou, nW);
    cvt_kernel<<<nW4 / 1024, 256>>>(w1, w1u, nW4);
    cvt_kernel<<<nW4 / 1024, 256>>>(w2, w2u, nW4);

    dim3 gQKV(QKVD / 128, BT / 128);  // (24, 32)
    dim3 gN1(DIMC / 128, BT / 128);   // (8, 32)
    dim3 gN4(HID  / 128, BT / 128);   // (32, 32)

    rmsnorm_kernel<<<BT, 256>>>(x, ga, xn);
    gemm_tf32<<<gQKV, 256, G_SMEM>>>(xn, wqkv, (float*)qkv, nullptr, BT, QKVD, DIMC, 2);
    attn_tf32<<<dim3(BB * NH, TT / 64), 128, ATT_SMEM>>>(qkv, ao);
    gemm_tf32<<<gN1, 256, G_SMEM>>>(ao, wou, x1, x, BT, DIMC, DIMC, 0);
    rmsnorm_kernel<<<BT, 256>>>(x1, gf, xn);
    gemm_tf32<<<gN4, 256, G_SMEM>>>(xn, w1u, (float*)hb, nullptr, BT, HID, DIMC, 3);
    gemm_tf32<<<gN1, 256, G_SMEM>>>(hb, w2u, out, x1, BT, DIMC, HID, 0);
}

// round 9
// speedup vs baseline: 2.4934x; 1.9592x over previous
#include <cuda_runtime.h>
#include <cuda_fp16.h>
#include <math.h>
#include <cstdint>

#define BB   2
#define TT   2048
#define BT   4096
#define DIMC 1024
#define NH   16
#define HD   64
#define HID  4096
#define QKVD 3072
#define EPSV 1e-6f

// ---------------- scratch ----------------------------------------------------
__device__ __half g_xn  [BT * DIMC];
__device__ __half g_qkv [BT * QKVD];
__device__ __half g_ao  [BT * DIMC];
__device__ float  g_x1  [BT * DIMC];
__device__ __half g_h   [BT * HID];
__device__ __half g_wqkv[DIMC * QKVD];   // [k][n] packed wq|wk|wv (wq scaled 1/8)
__device__ __half g_wou [DIMC * DIMC];
__device__ __half g_w1u [DIMC * HID];
__device__ __half g_w2u [HID * DIMC];

// ---------------- helpers -----------------------------------------------------
__device__ __forceinline__ unsigned h2pack(float lo, float hi) {
    __half2 t = __floats2half2_rn(lo, hi);
    return *(unsigned*)&t;
}
__device__ __forceinline__ uint32_t smem_u32(const void* p) {
    uint32_t a;
    asm("{ .reg .u64 t; cvta.to.shared.u64 t, %1; cvt.u32.u64 %0, t; }"
        : "=r"(a) : "l"(p));
    return a;
}
__device__ __forceinline__ void mma16(float* d, const unsigned* a, const unsigned* b) {
    asm volatile(
        "mma.sync.aligned.m16n8k16.row.col.f32.f16.f16.f32 "
        "{%0,%1,%2,%3}, {%4,%5,%6,%7}, {%8,%9}, {%0,%1,%2,%3};"
        : "+f"(d[0]), "+f"(d[1]), "+f"(d[2]), "+f"(d[3])
        : "r"(a[0]), "r"(a[1]), "r"(a[2]), "r"(a[3]), "r"(b[0]), "r"(b[1]));
}
__device__ __forceinline__ void ldsm4(uint32_t addr, unsigned* r) {
    asm volatile("ldmatrix.sync.aligned.m8n8.x4.shared.b16 {%0,%1,%2,%3}, [%4];"
        : "=r"(r[0]), "=r"(r[1]), "=r"(r[2]), "=r"(r[3]) : "r"(addr));
}
__device__ __forceinline__ void ldsm4t(uint32_t addr, unsigned* r) {
    asm volatile("ldmatrix.sync.aligned.m8n8.x4.trans.shared.b16 {%0,%1,%2,%3}, [%4];"
        : "=r"(r[0]), "=r"(r[1]), "=r"(r[2]), "=r"(r[3]) : "r"(addr));
}
__device__ __forceinline__ void cpasync16(uint32_t dst, const void* src) {
    asm volatile("cp.async.cg.shared.global [%0], [%1], 16;"
        :: "r"(dst), "l"(__cvta_generic_to_global(src)));
}
#define CP_COMMIT asm volatile("cp.async.commit_group;" ::: "memory")

// ---------------- weight conversion / packing ----------------------------------
__global__ void cvt_kernel(const float* __restrict__ src,
                           __half* __restrict__ dst, int n) {
    int i = (blockIdx.x * blockDim.x + threadIdx.x) * 4;
    if (i < n) {
        float4 v = *(const float4*)(src + i);
        uint2 u;
        u.x = h2pack(v.x, v.y);
        u.y = h2pack(v.z, v.w);
        *(uint2*)(dst + i) = u;
    }
}
__global__ void pack_qkv_kernel(const float* __restrict__ src,
                                __half* __restrict__ dst, int coff, float scale) {
    int i = (blockIdx.x * blockDim.x + threadIdx.x) * 4;
    int r = i >> 10, c = i & 1023;
    float4 v = *(const float4*)(src + i);
    uint2 u;
    u.x = h2pack(v.x * scale, v.y * scale);
    u.y = h2pack(v.z * scale, v.w * scale);
    *(uint2*)(dst + (size_t)r * QKVD + coff + c) = u;
}

// ---------------- RMSNorm (half output) ----------------------------------------
__global__ void rmsnorm_kernel(const float* __restrict__ x,
                               const float* __restrict__ g,
                               __half* __restrict__ y) {
    int row = blockIdx.x;
    int tid = threadIdx.x;
    const float* xr = x + (size_t)row * DIMC;
    float4 xv = *(const float4*)(xr + tid * 4);
    float s = xv.x * xv.x + xv.y * xv.y + xv.z * xv.z + xv.w * xv.w;
    #pragma unroll
    for (int off = 16; off; off >>= 1) s += __shfl_xor_sync(0xFFFFFFFFu, s, off);
    __shared__ float ws[8];
    __shared__ float snorm;
    if ((tid & 31) == 0) ws[tid >> 5] = s;
    __syncthreads();
    if (tid == 0) {
        float t = 0.f;
        #pragma unroll
        for (int i = 0; i < 8; i++) t += ws[i];
        snorm = rsqrtf(t * (1.0f / DIMC) + EPSV);
    }
    __syncthreads();
    float n = snorm;
    float4 gv = *(const float4*)(g + tid * 4);
    uint2 u;
    u.x = h2pack(xv.x * n * gv.x, xv.y * n * gv.y);
    u.y = h2pack(xv.z * n * gv.z, xv.w * n * gv.w);
    *(uint2*)(y + (size_t)row * DIMC + tid * 4) = u;
}

// ---------------- FP16 GEMM 128x128, K-chunk 64, all-cp.async ------------------
// stage s (32KB): A [128 m][64 k] half SW128 @ +0 (16KB),
//                 B [64 k][128 n] half (256B rows, swizzled) @ +16384 (16KB)
#define GSTAGE 32768
#define G_SMEM 65536
// mode bits: 1 = silu, 2 = half output
__global__ __launch_bounds__(256, 2)
void gemm_f16(const __half* __restrict__ A, const __half* __restrict__ B,
              float* __restrict__ C, const float* __restrict__ res,
              int M, int N, int K, int mode) {
    extern __shared__ char smc[];
    const uint32_t sbase = smem_u32(smc);
    const int tid = threadIdx.x;
    const int warp = tid >> 5, lane = tid & 31;
    const int lg = lane >> 2, ltg = lane & 3;
    const int wm = warp >> 2, wn = warp & 3;
    const int bm0 = blockIdx.y * 128, bn0 = blockIdx.x * 128;

    // A loader: chunk idx = tid + i*256 -> row (idx>>3), 16B col (idx&7)
    const int arow0 = tid >> 3, ac = tid & 7;
    const __half* Agp = A + (size_t)(bm0 + arow0) * K + ac * 8;
    const int asw = (ac * 16) ^ ((arow0 & 7) << 4);
    // B loader: chunk idx -> k row (idx>>4), 16B col (idx&15)
    const int brow0 = tid >> 4, bc = tid & 15;
    const __half* Bgp = B + (size_t)brow0 * N + bn0 + bc * 8;
    const int bsw = (bc * 16) ^ ((brow0 & 7) << 4);

    // fragment base offsets
    const int mat = lane >> 3, mrow = lane & 7;
    int aoff[4], boff[2];
    #pragma unroll
    for (int mt = 0; mt < 4; mt++) {
        int row = wm * 64 + mt * 16 + (mat & 1) * 8 + mrow;
        aoff[mt] = row * 128 + (((mat >> 1) << 4) ^ ((row & 7) << 4));
    }
    #pragma unroll
    for (int p = 0; p < 2; p++) {
        int kr = (mat & 1) * 8 + mrow;
        int nb = wn * 64 + p * 32 + ((mat >> 1) << 4);
        boff[p] = kr * 256 + (nb ^ ((kr & 7) << 4));
    }

    float acc[4][4][4];
    #pragma unroll
    for (int mt = 0; mt < 4; mt++)
        #pragma unroll
        for (int nt = 0; nt < 4; nt++)
            #pragma unroll
            for (int r = 0; r < 4; r++) acc[mt][nt][r] = 0.f;

    auto loadAB = [&](int kt, int buf) {
        uint32_t da = sbase + buf * GSTAGE;
        uint32_t db = da + 16384;
        #pragma unroll
        for (int i = 0; i < 4; i++)
            cpasync16(da + (arow0 + i * 32) * 128 + asw,
                      Agp + (size_t)kt * 64 + (size_t)i * 32 * K);
        #pragma unroll
        for (int i = 0; i < 4; i++)
            cpasync16(db + (brow0 + i * 16) * 256 + bsw,
                      Bgp + (size_t)(kt * 64 + i * 16) * N);
    };

    const int nkt = K >> 6;
    loadAB(0, 0); CP_COMMIT;
    loadAB(1, 1); CP_COMMIT;
    asm volatile("cp.async.wait_group 1;" ::: "memory");
    __syncthreads();

    for (int kt = 0; kt < nkt; kt++) {
        int buf = kt & 1;
        uint32_t sa = sbase + buf * GSTAGE;
        uint32_t sb = sa + 16384;
        #pragma unroll
        for (int kk = 0; kk < 4; kk++) {
            unsigned af[4][4], bf[2][4];
            #pragma unroll
            for (int mt = 0; mt < 4; mt++)
                ldsm4(sa + (aoff[mt] ^ (kk << 5)), af[mt]);
            #pragma unroll
            for (int p = 0; p < 2; p++)
                ldsm4t(sb + boff[p] + (kk << 12), bf[p]);
            #pragma unroll
            for (int mt = 0; mt < 4; mt++)
                #pragma unroll
                for (int nt = 0; nt < 4; nt++)
                    mma16(acc[mt][nt], af[mt], &bf[nt >> 1][(nt & 1) * 2]);
        }
        __syncthreads();
        if (kt + 2 < nkt) {
            loadAB(kt + 2, buf);
            CP_COMMIT;
            asm volatile("cp.async.wait_group 1;" ::: "memory");
        } else {
            asm volatile("cp.async.wait_group 0;" ::: "memory");
        }
        __syncthreads();
    }

    // epilogue: rows wm*64+mt*16+lg(+8), cols wn*32+nt*8+2*ltg
    #pragma unroll
    for (int mt = 0; mt < 4; mt++) {
        #pragma unroll
        for (int half = 0; half < 2; half++) {
            int r = bm0 + wm * 64 + mt * 16 + lg + half * 8;
            #pragma unroll
            for (int nt = 0; nt < 4; nt++) {
                int c = bn0 + wn * 32 + nt * 8 + 2 * ltg;
                float v0 = acc[mt][nt][half * 2 + 0];
                float v1 = acc[mt][nt][half * 2 + 1];
                if (mode & 1) {
                    v0 = v0 / (1.f + __expf(-v0));
                    v1 = v1 / (1.f + __expf(-v1));
                }
                if (res) {
                    float2 rv = *(const float2*)(res + (size_t)r * N + c);
                    v0 += rv.x; v1 += rv.y;
                }
                if (mode & 2) {
                    *(unsigned*)((__half*)C + (size_t)r * N + c) = h2pack(v0, v1);
                } else {
                    *(float2*)(C + (size_t)r * N + c) = make_float2(v0, v1);
                }
            }
        }
    }
}

// ---------------- Flash attention, fp16 mma, no P round-trip -------------------
__global__ void attn_f16(const __half* __restrict__ QKV,
                         __half* __restrict__ O) {
    __shared__ __align__(16) char smA[16384];
    char* Ksc = smA;
    char* Vsc = smA + 8192;
    const uint32_t ksb = smem_u32(Ksc);
    const uint32_t vsb = smem_u32(Vsc);

    int bh = blockIdx.x, qt = blockIdx.y;
    int b = bh >> 4, h = bh & 15;
    int q0 = qt * 64;
    int tid = threadIdx.x, warp = tid >> 5, lane = tid & 31;
    int g = lane >> 2, tg = lane & 3;
    int r0l = warp * 16 + g;
    const int mat = lane >> 3, mrow = lane & 7;

    const __half* Qb = QKV + ((size_t)(b * TT + q0)) * QKVD + h * HD;
    const __half* Kb = QKV + ((size_t)(b * TT)) * QKVD + DIMC + h * HD;
    const __half* Vb = QKV + ((size_t)(b * TT)) * QKVD + 2 * DIMC + h * HD;

    // Q A-fragments (wq pre-scaled by 1/8): contiguous half2 pairs
    unsigned qa[4][4];
    #pragma unroll
    for (int kk = 0; kk < 4; kk++) {
        qa[kk][0] = *(const unsigned*)(Qb + (size_t)r0l * QKVD + kk * 16 + 2 * tg);
        qa[kk][1] = *(const unsigned*)(Qb + (size_t)(r0l + 8) * QKVD + kk * 16 + 2 * tg);
        qa[kk][2] = *(const unsigned*)(Qb + (size_t)r0l * QKVD + kk * 16 + 8 + 2 * tg);
        qa[kk][3] = *(const unsigned*)(Qb + (size_t)(r0l + 8) * QKVD + kk * 16 + 8 + 2 * tg);
    }

    // fragment offsets
    int boffK[4], voff[4];
    #pragma unroll
    for (int p = 0; p < 4; p++) {
        int n = p * 16 + (mat >> 1) * 8 + mrow;          // key row (acts as n)
        boffK[p] = n * 128 + ((((unsigned)(mat & 1)) << 4) ^ ((n & 7) << 4));
        int sr = (mat & 1) * 8 + mrow;                   // key row within k16 (trans)
        int db = (2 * p + (mat >> 1)) * 16;              // d-byte
        voff[p] = sr * 128 + (db ^ ((sr & 7) << 4));
    }

    float oacc[8][4];
    #pragma unroll
    for (int nt = 0; nt < 8; nt++)
        #pragma unroll
        for (int r = 0; r < 4; r++) oacc[nt][r] = 0.f;
    float m0 = -1e30f, m1 = -1e30f, l0 = 0.f, l1 = 0.f;
    int r0g = q0 + r0l, r1g = r0g + 8;

    for (int s0 = 0; s0 <= q0; s0 += 64) {
        // load K,V tiles (swizzled 16B copies)
        for (int i = tid; i < 512; i += 128) {
            int r = i >> 3, c = i & 7;
            int sw = (c * 16) ^ ((r & 7) << 4);
            *(uint4*)(Ksc + r * 128 + sw) =
                *(const uint4*)(Kb + (size_t)(s0 + r) * QKVD + c * 8);
            *(uint4*)(Vsc + r * 128 + sw) =
                *(const uint4*)(Vb + (size_t)(s0 + r) * QKVD + c * 8);
        }
        __syncthreads();

        // S = Q K^T
        float sc[8][4];
        #pragma unroll
        for (int nt = 0; nt < 8; nt++)
            #pragma unroll
            for (int r = 0; r < 4; r++) sc[nt][r] = 0.f;
        #pragma unroll
        for (int kk = 0; kk < 4; kk++) {
            #pragma unroll
            for (int p = 0; p < 4; p++) {
                unsigned bf[4];
                ldsm4(ksb + (boffK[p] ^ (kk << 5)), bf);
                mma16(sc[2 * p], qa[kk], bf);
                mma16(sc[2 * p + 1], qa[kk], bf + 2);
            }
        }

        // causal mask (diagonal tile only)
        if (s0 == q0) {
            #pragma unroll
            for (int nt = 0; nt < 8; nt++) {
                int j = s0 + nt * 8 + 2 * tg;
                if (j     > r0g) sc[nt][0] = -1e30f;
                if (j + 1 > r0g) sc[nt][1] = -1e30f;
                if (j     > r1g) sc[nt][2] = -1e30f;
                if (j + 1 > r1g) sc[nt][3] = -1e30f;
            }
        }

        // online softmax
        float mx0 = -1e30f, mx1 = -1e30f;
        #pragma unroll
        for (int nt = 0; nt < 8; nt++) {
            mx0 = fmaxf(mx0, fmaxf(sc[nt][0], sc[nt][1]));
            mx1 = fmaxf(mx1, fmaxf(sc[nt][2], sc[nt][3]));
        }
        mx0 = fmaxf(mx0, __shfl_xor_sync(0xFFFFFFFFu, mx0, 1));
        mx0 = fmaxf(mx0, __shfl_xor_sync(0xFFFFFFFFu, mx0, 2));
        mx1 = fmaxf(mx1, __shfl_xor_sync(0xFFFFFFFFu, mx1, 1));
        mx1 = fmaxf(mx1, __shfl_xor_sync(0xFFFFFFFFu, mx1, 2));
        float mn0 = fmaxf(m0, mx0), mn1 = fmaxf(m1, mx1);
        float al0 = __expf(m0 - mn0), al1 = __expf(m1 - mn1);
        float s0r = 0.f, s1r = 0.f;
        #pragma unroll
        for (int nt = 0; nt < 8; nt++) {
            sc[nt][0] = __expf(sc[nt][0] - mn0);
            sc[nt][1] = __expf(sc[nt][1] - mn0);
            sc[nt][2] = __expf(sc[nt][2] - mn1);
            sc[nt][3] = __expf(sc[nt][3] - mn1);
            s0r += sc[nt][0] + sc[nt][1];
            s1r += sc[nt][2] + sc[nt][3];
        }
        s0r += __shfl_xor_sync(0xFFFFFFFFu, s0r, 1);
        s0r += __shfl_xor_sync(0xFFFFFFFFu, s0r, 2);
        s1r += __shfl_xor_sync(0xFFFFFFFFu, s1r, 1);
        s1r += __shfl_xor_sync(0xFFFFFFFFu, s1r, 2);
        l0 = l0 * al0 + s0r;
        l1 = l1 * al1 + s1r;
        m0 = mn0; m1 = mn1;
        #pragma unroll
        for (int nt = 0; nt < 8; nt++) {
            oacc[nt][0] *= al0; oacc[nt][1] *= al0;
            oacc[nt][2] *= al1; oacc[nt][3] *= al1;
        }

        // O += P @ V : P fragments straight from registers
        #pragma unroll
        for (int kk = 0; kk < 4; kk++) {
            unsigned pa[4];
            pa[0] = h2pack(sc[2 * kk][0],     sc[2 * kk][1]);
            pa[1] = h2pack(sc[2 * kk][2],     sc[2 * kk][3]);
            pa[2] = h2pack(sc[2 * kk + 1][0], sc[2 * kk + 1][1]);
            pa[3] = h2pack(sc[2 * kk + 1][2], sc[2 * kk + 1][3]);
            #pragma unroll
            for (int p = 0; p < 4; p++) {
                unsigned bf[4];
                ldsm4t(vsb + voff[p] + (kk << 11), bf);
                mma16(oacc[2 * p], pa, bf);
                mma16(oacc[2 * p + 1], pa, bf + 2);
            }
        }
        __syncthreads();
    }

    float il0 = 1.f / l0, il1 = 1.f / l1;
    __half* Ob = O + ((size_t)(b * TT + q0 + r0l)) * DIMC + h * HD;
    #pragma unroll
    for (int nt = 0; nt < 8; nt++) {
        *(unsigned*)(Ob + nt * 8 + 2 * tg) =
            h2pack(oacc[nt][0] * il0, oacc[nt][1] * il0);
        *(unsigned*)(Ob + (size_t)8 * DIMC + nt * 8 + 2 * tg) =
            h2pack(oacc[nt][2] * il1, oacc[nt][3] * il1);
    }
}

// ---------------- launcher ----------------------------------------------------
extern "C" void kernel_launch(void* const* d_in, const int* in_sizes, int n_in,
                              void* d_out, int out_size) {
    const float* x  = (const float*)d_in[0];
    const float* wq = (const float*)d_in[2];
    const float* wk = (const float*)d_in[3];
    const float* wv = (const float*)d_in[4];
    const float* wo = (const float*)d_in[5];
    const float* w1 = (const float*)d_in[6];
    const float* w2 = (const float*)d_in[7];
    const float* ga = (const float*)d_in[8];
    const float* gf = (const float*)d_in[9];
    float* out = (float*)d_out;

    __half *xn, *qkv, *ao, *hb, *wqkv, *wou, *w1u, *w2u;
    float *x1;
    cudaGetSymbolAddress((void**)&xn,   g_xn);
    cudaGetSymbolAddress((void**)&qkv,  g_qkv);
    cudaGetSymbolAddress((void**)&ao,   g_ao);
    cudaGetSymbolAddress((void**)&x1,   g_x1);
    cudaGetSymbolAddress((void**)&hb,   g_h);
    cudaGetSymbolAddress((void**)&wqkv, g_wqkv);
    cudaGetSymbolAddress((void**)&wou,  g_wou);
    cudaGetSymbolAddress((void**)&w1u,  g_w1u);
    cudaGetSymbolAddress((void**)&w2u,  g_w2u);

    cudaFuncSetAttribute(gemm_f16,
                         cudaFuncAttributeMaxDynamicSharedMemorySize, G_SMEM);

    const int nW = DIMC * DIMC, nW4 = DIMC * HID;
    pack_qkv_kernel<<<nW / 1024, 256>>>(wq, wqkv, 0,        0.125f);
    pack_qkv_kernel<<<nW / 1024, 256>>>(wk, wqkv, DIMC,     1.0f);
    pack_qkv_kernel<<<nW / 1024, 256>>>(wv, wqkv, 2 * DIMC, 1.0f);
    cvt_kernel<<<nW / 1024, 256>>>(wo, wou, nW);
    cvt_kernel<<<nW4 / 1024, 256>>>(w1, w1u, nW4);
    cvt_kernel<<<nW4 / 1024, 256>>>(w2, w2u, nW4);

    dim3 gQKV(QKVD / 128, BT / 128);  // (24, 32)
    dim3 gN1(DIMC / 128, BT / 128);   // (8, 32)
    dim3 gN4(HID  / 128, BT / 128);   // (32, 32)

    rmsnorm_kernel<<<BT, 256>>>(x, ga, xn);
    gemm_f16<<<gQKV, 256, G_SMEM>>>(xn, wqkv, (float*)qkv, nullptr, BT, QKVD, DIMC, 2);
    attn_f16<<<dim3(BB * NH, TT / 64), 128>>>(qkv, ao);
    gemm_f16<<<gN1, 256, G_SMEM>>>(ao, wou, x1, x, BT, DIMC, DIMC, 0);
    rmsnorm_kernel<<<BT, 256>>>(x1, gf, xn);
    gemm_f16<<<gN4, 256, G_SMEM>>>(xn, w1u, (float*)hb, nullptr, BT, HID, DIMC, 3);
    gemm_f16<<<gN1, 256, G_SMEM>>>(hb, w2u, out, x1, BT, DIMC, HID, 0);
}

// round 10
// speedup vs baseline: 2.5193x; 1.0104x over previous
#include <cuda_runtime.h>
#include <cuda_fp16.h>
#include <math.h>
#include <cstdint>

#define BB   2
#define TT   2048
#define BT   4096
#define DIMC 1024
#define NH   16
#define HD   64
#define HID  4096
#define QKVD 3072
#define EPSV 1e-6f

// ---------------- scratch ----------------------------------------------------
__device__ __half g_xn  [BT * DIMC];
__device__ __half g_qkv [BT * QKVD];
__device__ __half g_ao  [BT * DIMC];
__device__ float  g_x1  [BT * DIMC];
__device__ __half g_h   [BT * HID];
__device__ __half g_wqkv[DIMC * QKVD];   // [k][n] packed wq|wk|wv (wq scaled 1/8)
__device__ __half g_wou [DIMC * DIMC];
__device__ __half g_w1u [DIMC * HID];
__device__ __half g_w2u [HID * DIMC];

// ---------------- helpers -----------------------------------------------------
__device__ __forceinline__ unsigned h2pack(float lo, float hi) {
    __half2 t = __floats2half2_rn(lo, hi);
    return *(unsigned*)&t;
}
__device__ __forceinline__ uint32_t smem_u32(const void* p) {
    uint32_t a;
    asm("{ .reg .u64 t; cvta.to.shared.u64 t, %1; cvt.u32.u64 %0, t; }"
        : "=r"(a) : "l"(p));
    return a;
}
__device__ __forceinline__ void mma16(float* d, const unsigned* a, const unsigned* b) {
    asm volatile(
        "mma.sync.aligned.m16n8k16.row.col.f32.f16.f16.f32 "
        "{%0,%1,%2,%3}, {%4,%5,%6,%7}, {%8,%9}, {%0,%1,%2,%3};"
        : "+f"(d[0]), "+f"(d[1]), "+f"(d[2]), "+f"(d[3])
        : "r"(a[0]), "r"(a[1]), "r"(a[2]), "r"(a[3]), "r"(b[0]), "r"(b[1]));
}
__device__ __forceinline__ void ldsm4(uint32_t addr, unsigned* r) {
    asm volatile("ldmatrix.sync.aligned.m8n8.x4.shared.b16 {%0,%1,%2,%3}, [%4];"
        : "=r"(r[0]), "=r"(r[1]), "=r"(r[2]), "=r"(r[3]) : "r"(addr));
}
__device__ __forceinline__ void ldsm4t(uint32_t addr, unsigned* r) {
    asm volatile("ldmatrix.sync.aligned.m8n8.x4.trans.shared.b16 {%0,%1,%2,%3}, [%4];"
        : "=r"(r[0]), "=r"(r[1]), "=r"(r[2]), "=r"(r[3]) : "r"(addr));
}
__device__ __forceinline__ void cpasync16(uint32_t dst, const void* src) {
    asm volatile("cp.async.cg.shared.global [%0], [%1], 16;"
        :: "r"(dst), "l"(__cvta_generic_to_global(src)));
}
#define CP_COMMIT asm volatile("cp.async.commit_group;" ::: "memory")

// ---------------- weight conversion / packing (16 elems/thread) ----------------
__global__ void cvt_kernel(const float* __restrict__ src,
                           __half* __restrict__ dst, int n) {
    int i = (blockIdx.x * blockDim.x + threadIdx.x) * 16;
    if (i < n) {
        float4 v0 = *(const float4*)(src + i);
        float4 v1 = *(const float4*)(src + i + 4);
        float4 v2 = *(const float4*)(src + i + 8);
        float4 v3 = *(const float4*)(src + i + 12);
        uint4 a, b;
        a.x = h2pack(v0.x, v0.y); a.y = h2pack(v0.z, v0.w);
        a.z = h2pack(v1.x, v1.y); a.w = h2pack(v1.z, v1.w);
        b.x = h2pack(v2.x, v2.y); b.y = h2pack(v2.z, v2.w);
        b.z = h2pack(v3.x, v3.y); b.w = h2pack(v3.z, v3.w);
        *(uint4*)(dst + i) = a;
        *(uint4*)(dst + i + 8) = b;
    }
}
__global__ void pack_qkv_kernel(const float* __restrict__ src,
                                __half* __restrict__ dst, int coff, float scale) {
    int i = (blockIdx.x * blockDim.x + threadIdx.x) * 16;   // 16 elems, same row
    int r = i >> 10, c = i & 1023;
    __half* drow = dst + (size_t)r * QKVD + coff + c;
    float4 v0 = *(const float4*)(src + i);
    float4 v1 = *(const float4*)(src + i + 4);
    float4 v2 = *(const float4*)(src + i + 8);
    float4 v3 = *(const float4*)(src + i + 12);
    uint4 a, b;
    a.x = h2pack(v0.x * scale, v0.y * scale); a.y = h2pack(v0.z * scale, v0.w * scale);
    a.z = h2pack(v1.x * scale, v1.y * scale); a.w = h2pack(v1.z * scale, v1.w * scale);
    b.x = h2pack(v2.x * scale, v2.y * scale); b.y = h2pack(v2.z * scale, v2.w * scale);
    b.z = h2pack(v3.x * scale, v3.y * scale); b.w = h2pack(v3.z * scale, v3.w * scale);
    *(uint4*)drow = a;
    *(uint4*)(drow + 8) = b;
}

// ---------------- RMSNorm (half output) ----------------------------------------
__global__ void rmsnorm_kernel(const float* __restrict__ x,
                               const float* __restrict__ g,
                               __half* __restrict__ y) {
    int row = blockIdx.x;
    int tid = threadIdx.x;
    const float* xr = x + (size_t)row * DIMC;
    float4 xv = *(const float4*)(xr + tid * 4);
    float s = xv.x * xv.x + xv.y * xv.y + xv.z * xv.z + xv.w * xv.w;
    #pragma unroll
    for (int off = 16; off; off >>= 1) s += __shfl_xor_sync(0xFFFFFFFFu, s, off);
    __shared__ float ws[8];
    __shared__ float snorm;
    if ((tid & 31) == 0) ws[tid >> 5] = s;
    __syncthreads();
    if (tid == 0) {
        float t = 0.f;
        #pragma unroll
        for (int i = 0; i < 8; i++) t += ws[i];
        snorm = rsqrtf(t * (1.0f / DIMC) + EPSV);
    }
    __syncthreads();
    float n = snorm;
    float4 gv = *(const float4*)(g + tid * 4);
    uint2 u;
    u.x = h2pack(xv.x * n * gv.x, xv.y * n * gv.y);
    u.y = h2pack(xv.z * n * gv.z, xv.w * n * gv.w);
    *(uint2*)(y + (size_t)row * DIMC + tid * 4) = u;
}

// ---------------- FP16 GEMM 128x128, K-chunk 64, 3-stage ring ------------------
// stage (32KB): A [128 m][64 k] half SW128 @ +0, B [64 k][128 n] @ +16384
#define GSTAGE 32768
#define G_SMEM (3 * GSTAGE)
// mode bits: 1 = silu, 2 = half output
__global__ __launch_bounds__(256, 2)
void gemm_f16(const __half* __restrict__ A, const __half* __restrict__ B,
              float* __restrict__ C, const float* __restrict__ res,
              int M, int N, int K, int mode) {
    extern __shared__ char smc[];
    const uint32_t sbase = smem_u32(smc);
    const int tid = threadIdx.x;
    const int warp = tid >> 5, lane = tid & 31;
    const int lg = lane >> 2, ltg = lane & 3;
    const int wm = warp >> 2, wn = warp & 3;
    const int bm0 = blockIdx.y * 128, bn0 = blockIdx.x * 128;

    const int arow0 = tid >> 3, ac = tid & 7;
    const __half* Agp = A + (size_t)(bm0 + arow0) * K + ac * 8;
    const int asw = (ac * 16) ^ ((arow0 & 7) << 4);
    const int brow0 = tid >> 4, bc = tid & 15;
    const __half* Bgp = B + (size_t)brow0 * N + bn0 + bc * 8;
    const int bsw = (bc * 16) ^ ((brow0 & 7) << 4);

    const int mat = lane >> 3, mrow = lane & 7;
    int aoff[4], boff[2];
    #pragma unroll
    for (int mt = 0; mt < 4; mt++) {
        int row = wm * 64 + mt * 16 + (mat & 1) * 8 + mrow;
        aoff[mt] = row * 128 + (((mat >> 1) << 4) ^ ((row & 7) << 4));
    }
    #pragma unroll
    for (int p = 0; p < 2; p++) {
        int kr = (mat & 1) * 8 + mrow;
        int nb = wn * 64 + p * 32 + ((mat >> 1) << 4);
        boff[p] = kr * 256 + (nb ^ ((kr & 7) << 4));
    }

    float acc[4][4][4];
    #pragma unroll
    for (int mt = 0; mt < 4; mt++)
        #pragma unroll
        for (int nt = 0; nt < 4; nt++)
            #pragma unroll
            for (int r = 0; r < 4; r++) acc[mt][nt][r] = 0.f;

    auto loadAB = [&](int kt, int slot) {
        uint32_t da = sbase + slot * GSTAGE;
        uint32_t db = da + 16384;
        #pragma unroll
        for (int i = 0; i < 4; i++)
            cpasync16(da + (arow0 + i * 32) * 128 + asw,
                      Agp + (size_t)kt * 64 + (size_t)i * 32 * K);
        #pragma unroll
        for (int i = 0; i < 4; i++)
            cpasync16(db + (brow0 + i * 16) * 256 + bsw,
                      Bgp + (size_t)(kt * 64 + i * 16) * N);
    };

    const int nkt = K >> 6;
    loadAB(0, 0); CP_COMMIT;
    loadAB(1, 1); CP_COMMIT;

    int slot = 0;
    for (int kt = 0; kt < nkt; kt++) {
        asm volatile("cp.async.wait_group 1;" ::: "memory");
        __syncthreads();
        if (kt + 2 < nkt) {
            int s2 = slot + 2; if (s2 >= 3) s2 -= 3;
            loadAB(kt + 2, s2);
            CP_COMMIT;
        }
        uint32_t sa = sbase + slot * GSTAGE;
        uint32_t sb = sa + 16384;
        #pragma unroll
        for (int kk = 0; kk < 4; kk++) {
            unsigned af[4][4], bf[2][4];
            #pragma unroll
            for (int mt = 0; mt < 4; mt++)
                ldsm4(sa + (aoff[mt] ^ (kk << 5)), af[mt]);
            #pragma unroll
            for (int p = 0; p < 2; p++)
                ldsm4t(sb + boff[p] + (kk << 12), bf[p]);
            #pragma unroll
            for (int mt = 0; mt < 4; mt++)
                #pragma unroll
                for (int nt = 0; nt < 4; nt++)
                    mma16(acc[mt][nt], af[mt], &bf[nt >> 1][(nt & 1) * 2]);
        }
        if (++slot >= 3) slot = 0;
    }

    // epilogue: rows wm*64+mt*16+lg(+8), cols wn*32+nt*8+2*ltg
    #pragma unroll
    for (int mt = 0; mt < 4; mt++) {
        #pragma unroll
        for (int half = 0; half < 2; half++) {
            int r = bm0 + wm * 64 + mt * 16 + lg + half * 8;
            #pragma unroll
            for (int nt = 0; nt < 4; nt++) {
                int c = bn0 + wn * 32 + nt * 8 + 2 * ltg;
                float v0 = acc[mt][nt][half * 2 + 0];
                float v1 = acc[mt][nt][half * 2 + 1];
                if (mode & 1) {
                    v0 = v0 / (1.f + __expf(-v0));
                    v1 = v1 / (1.f + __expf(-v1));
                }
                if (res) {
                    float2 rv = *(const float2*)(res + (size_t)r * N + c);
                    v0 += rv.x; v1 += rv.y;
                }
                if (mode & 2) {
                    *(unsigned*)((__half*)C + (size_t)r * N + c) = h2pack(v0, v1);
                } else {
                    *(float2*)(C + (size_t)r * N + c) = make_float2(v0, v1);
                }
            }
        }
    }
}

// ---------------- Flash attention, fp16 mma, no P round-trip -------------------
__global__ void attn_f16(const __half* __restrict__ QKV,
                         __half* __restrict__ O) {
    __shared__ __align__(16) char smA[16384];
    char* Ksc = smA;
    char* Vsc = smA + 8192;
    const uint32_t ksb = smem_u32(Ksc);
    const uint32_t vsb = smem_u32(Vsc);

    int bh = blockIdx.x, qt = blockIdx.y;
    int b = bh >> 4, h = bh & 15;
    int q0 = qt * 64;
    int tid = threadIdx.x, warp = tid >> 5, lane = tid & 31;
    int g = lane >> 2, tg = lane & 3;
    int r0l = warp * 16 + g;
    const int mat = lane >> 3, mrow = lane & 7;

    const __half* Qb = QKV + ((size_t)(b * TT + q0)) * QKVD + h * HD;
    const __half* Kb = QKV + ((size_t)(b * TT)) * QKVD + DIMC + h * HD;
    const __half* Vb = QKV + ((size_t)(b * TT)) * QKVD + 2 * DIMC + h * HD;

    unsigned qa[4][4];
    #pragma unroll
    for (int kk = 0; kk < 4; kk++) {
        qa[kk][0] = *(const unsigned*)(Qb + (size_t)r0l * QKVD + kk * 16 + 2 * tg);
        qa[kk][1] = *(const unsigned*)(Qb + (size_t)(r0l + 8) * QKVD + kk * 16 + 2 * tg);
        qa[kk][2] = *(const unsigned*)(Qb + (size_t)r0l * QKVD + kk * 16 + 8 + 2 * tg);
        qa[kk][3] = *(const unsigned*)(Qb + (size_t)(r0l + 8) * QKVD + kk * 16 + 8 + 2 * tg);
    }

    int boffK[4], voff[4];
    #pragma unroll
    for (int p = 0; p < 4; p++) {
        int n = p * 16 + (mat >> 1) * 8 + mrow;
        boffK[p] = n * 128 + ((((unsigned)(mat & 1)) << 4) ^ ((n & 7) << 4));
        int sr = (mat & 1) * 8 + mrow;
        int db = (2 * p + (mat >> 1)) * 16;
        voff[p] = sr * 128 + (db ^ ((sr & 7) << 4));
    }

    float oacc[8][4];
    #pragma unroll
    for (int nt = 0; nt < 8; nt++)
        #pragma unroll
        for (int r = 0; r < 4; r++) oacc[nt][r] = 0.f;
    float m0 = -1e30f, m1 = -1e30f, l0 = 0.f, l1 = 0.f;
    int r0g = q0 + r0l, r1g = r0g + 8;

    for (int s0 = 0; s0 <= q0; s0 += 64) {
        for (int i = tid; i < 512; i += 128) {
            int r = i >> 3, c = i & 7;
            int sw = (c * 16) ^ ((r & 7) << 4);
            *(uint4*)(Ksc + r * 128 + sw) =
                *(const uint4*)(Kb + (size_t)(s0 + r) * QKVD + c * 8);
            *(uint4*)(Vsc + r * 128 + sw) =
                *(const uint4*)(Vb + (size_t)(s0 + r) * QKVD + c * 8);
        }
        __syncthreads();

        float sc[8][4];
        #pragma unroll
        for (int nt = 0; nt < 8; nt++)
            #pragma unroll
            for (int r = 0; r < 4; r++) sc[nt][r] = 0.f;
        #pragma unroll
        for (int kk = 0; kk < 4; kk++) {
            #pragma unroll
            for (int p = 0; p < 4; p++) {
                unsigned bf[4];
                ldsm4(ksb + (boffK[p] ^ (kk << 5)), bf);
                mma16(sc[2 * p], qa[kk], bf);
                mma16(sc[2 * p + 1], qa[kk], bf + 2);
            }
        }

        if (s0 == q0) {
            #pragma unroll
            for (int nt = 0; nt < 8; nt++) {
                int j = s0 + nt * 8 + 2 * tg;
                if (j     > r0g) sc[nt][0] = -1e30f;
                if (j + 1 > r0g) sc[nt][1] = -1e30f;
                if (j     > r1g) sc[nt][2] = -1e30f;
                if (j + 1 > r1g) sc[nt][3] = -1e30f;
            }
        }

        float mx0 = -1e30f, mx1 = -1e30f;
        #pragma unroll
        for (int nt = 0; nt < 8; nt++) {
            mx0 = fmaxf(mx0, fmaxf(sc[nt][0], sc[nt][1]));
            mx1 = fmaxf(mx1, fmaxf(sc[nt][2], sc[nt][3]));
        }
        mx0 = fmaxf(mx0, __shfl_xor_sync(0xFFFFFFFFu, mx0, 1));
        mx0 = fmaxf(mx0, __shfl_xor_sync(0xFFFFFFFFu, mx0, 2));
        mx1 = fmaxf(mx1, __shfl_xor_sync(0xFFFFFFFFu, mx1, 1));
        mx1 = fmaxf(mx1, __shfl_xor_sync(0xFFFFFFFFu, mx1, 2));
        float mn0 = fmaxf(m0, mx0), mn1 = fmaxf(m1, mx1);
        float al0 = __expf(m0 - mn0), al1 = __expf(m1 - mn1);
        float s0r = 0.f, s1r = 0.f;
        #pragma unroll
        for (int nt = 0; nt < 8; nt++) {
            sc[nt][0] = __expf(sc[nt][0] - mn0);
            sc[nt][1] = __expf(sc[nt][1] - mn0);
            sc[nt][2] = __expf(sc[nt][2] - mn1);
            sc[nt][3] = __expf(sc[nt][3] - mn1);
            s0r += sc[nt][0] + sc[nt][1];
            s1r += sc[nt][2] + sc[nt][3];
        }
        s0r += __shfl_xor_sync(0xFFFFFFFFu, s0r, 1);
        s0r += __shfl_xor_sync(0xFFFFFFFFu, s0r, 2);
        s1r += __shfl_xor_sync(0xFFFFFFFFu, s1r, 1);
        s1r += __shfl_xor_sync(0xFFFFFFFFu, s1r, 2);
        l0 = l0 * al0 + s0r;
        l1 = l1 * al1 + s1r;
        m0 = mn0; m1 = mn1;
        #pragma unroll
        for (int nt = 0; nt < 8; nt++) {
            oacc[nt][0] *= al0; oacc[nt][1] *= al0;
            oacc[nt][2] *= al1; oacc[nt][3] *= al1;
        }

        #pragma unroll
        for (int kk = 0; kk < 4; kk++) {
            unsigned pa[4];
            pa[0] = h2pack(sc[2 * kk][0],     sc[2 * kk][1]);
            pa[1] = h2pack(sc[2 * kk][2],     sc[2 * kk][3]);
            pa[2] = h2pack(sc[2 * kk + 1][0], sc[2 * kk + 1][1]);
            pa[3] = h2pack(sc[2 * kk + 1][2], sc[2 * kk + 1][3]);
            #pragma unroll
            for (int p = 0; p < 4; p++) {
                unsigned bf[4];
                ldsm4t(vsb + voff[p] + (kk << 11), bf);
                mma16(oacc[2 * p], pa, bf);
                mma16(oacc[2 * p + 1], pa, bf + 2);
            }
        }
        __syncthreads();
    }

    float il0 = 1.f / l0, il1 = 1.f / l1;
    __half* Ob = O + ((size_t)(b * TT + q0 + r0l)) * DIMC + h * HD;
    #pragma unroll
    for (int nt = 0; nt < 8; nt++) {
        *(unsigned*)(Ob + nt * 8 + 2 * tg) =
            h2pack(oacc[nt][0] * il0, oacc[nt][1] * il0);
        *(unsigned*)(Ob + (size_t)8 * DIMC + nt * 8 + 2 * tg) =
            h2pack(oacc[nt][2] * il1, oacc[nt][3] * il1);
    }
}

// ---------------- launcher ----------------------------------------------------
extern "C" void kernel_launch(void* const* d_in, const int* in_sizes, int n_in,
                              void* d_out, int out_size) {
    const float* x  = (const float*)d_in[0];
    const float* wq = (const float*)d_in[2];
    const float* wk = (const float*)d_in[3];
    const float* wv = (const float*)d_in[4];
    const float* wo = (const float*)d_in[5];
    const float* w1 = (const float*)d_in[6];
    const float* w2 = (const float*)d_in[7];
    const float* ga = (const float*)d_in[8];
    const float* gf = (const float*)d_in[9];
    float* out = (float*)d_out;

    __half *xn, *qkv, *ao, *hb, *wqkv, *wou, *w1u, *w2u;
    float *x1;
    cudaGetSymbolAddress((void**)&xn,   g_xn);
    cudaGetSymbolAddress((void**)&qkv,  g_qkv);
    cudaGetSymbolAddress((void**)&ao,   g_ao);
    cudaGetSymbolAddress((void**)&x1,   g_x1);
    cudaGetSymbolAddress((void**)&hb,   g_h);
    cudaGetSymbolAddress((void**)&wqkv, g_wqkv);
    cudaGetSymbolAddress((void**)&wou,  g_wou);
    cudaGetSymbolAddress((void**)&w1u,  g_w1u);
    cudaGetSymbolAddress((void**)&w2u,  g_w2u);

    cudaFuncSetAttribute(gemm_f16,
                         cudaFuncAttributeMaxDynamicSharedMemorySize, G_SMEM);

    const int nW = DIMC * DIMC, nW4 = DIMC * HID;
    pack_qkv_kernel<<<nW / 4096, 256>>>(wq, wqkv, 0,        0.125f);
    pack_qkv_kernel<<<nW / 4096, 256>>>(wk, wqkv, DIMC,     1.0f);
    pack_qkv_kernel<<<nW / 4096, 256>>>(wv, wqkv, 2 * DIMC, 1.0f);
    cvt_kernel<<<nW / 4096, 256>>>(wo, wou, nW);
    cvt_kernel<<<nW4 / 4096, 256>>>(w1, w1u, nW4);
    cvt_kernel<<<nW4 / 4096, 256>>>(w2, w2u, nW4);

    dim3 gQKV(QKVD / 128, BT / 128);  // (24, 32)
    dim3 gN1(DIMC / 128, BT / 128);   // (8, 32)
    dim3 gN4(HID  / 128, BT / 128);   // (32, 32)

    rmsnorm_kernel<<<BT, 256>>>(x, ga, xn);
    gemm_f16<<<gQKV, 256, G_SMEM>>>(xn, wqkv, (float*)qkv, nullptr, BT, QKVD, DIMC, 2);
    attn_f16<<<dim3(BB * NH, TT / 64), 128>>>(qkv, ao);
    gemm_f16<<<gN1, 256, G_SMEM>>>(ao, wou, x1, x, BT, DIMC, DIMC, 0);
    rmsnorm_kernel<<<BT, 256>>>(x1, gf, xn);
    gemm_f16<<<gN4, 256, G_SMEM>>>(xn, w1u, (float*)hb, nullptr, BT, HID, DIMC, 3);
    gemm_f16<<<gN1, 256, G_SMEM>>>(hb, w2u, out, x1, BT, DIMC, HID, 0);
}